// round 8
// baseline (speedup 1.0000x reference)
#include <cuda_runtime.h>
#include <cuda_bf16.h>
#include <cstdint>

// Problem constants
#define LDm   16384
#define LUm   65536
#define NNm   8
#define DIN   256
#define DOUT  128
#define M_ROWS (LDm * NNm)            // 131072 MLP rows
#define OUT_ROWS ((long)LUm * NNm)    // 524288 output rows

// Arch-specific (sm_103a/sm_100a) pass?
#if defined(__CUDA_ARCH__) && (defined(__CUDA_ARCH_FEAT_SM103_ALL) || \
    defined(__CUDA_ARCH_FEAT_SM100_ALL) || \
    (defined(__CUDA_ARCH_SPECIFIC__) && (__CUDA_ARCH_SPECIFIC__ >= 1000)))
#define HAS_TCGEN05 1
#else
#define HAS_TCGEN05 0
#endif

// Scratch: h = relu(x@W1+b1)@W2+b2  [LD, N, D_OUT] (64 MB)
__device__ __align__(128) float g_h[(size_t)M_ROWS * DOUT];
// Precomputed bf16 hi/lo splits of W1^T, W2^T (B operands, N x K, K-major)
__device__ __align__(16) __nv_bfloat16 g_w1t_hi[DOUT * DIN];
__device__ __align__(16) __nv_bfloat16 g_w1t_lo[DOUT * DIN];
__device__ __align__(16) __nv_bfloat16 g_w2t_hi[DOUT * DOUT];
__device__ __align__(16) __nv_bfloat16 g_w2t_lo[DOUT * DOUT];

// SMEM layout (tcgen05 path): double-buffered A stages + single B buffer
#define SM_A0HI 1024
#define SM_A0LO (SM_A0HI + 16384)    // 17408
#define SM_A1HI (SM_A0LO + 16384)    // 33792
#define SM_A1LO (SM_A1HI + 16384)    // 50176
#define SM_BHI  (SM_A1LO + 16384)    // 66560
#define SM_BLO  (SM_BHI + 16384)     // 82944
#define SM_B1   (SM_BLO + 16384)     // 99328
#define SM_B2   (SM_B1 + 512)        // 99840
#define SMEM_TOTAL 100352

// ---------------------------------------------------------------------------
// Pre-kernel: split W1^T / W2^T into bf16 hi/lo
// ---------------------------------------------------------------------------
__global__ void wsplit_kernel(const float* __restrict__ W1,
                              const float* __restrict__ W2)
{
    int t = blockIdx.x * blockDim.x + threadIdx.x;
    if (t < DOUT * DIN) {                   // W1^T: [n][k], n<128, k<256
        int n = t >> 8, k = t & 255;
        float x = W1[k * DOUT + n];
        uint32_t b = __float_as_uint(x);
        float hf = __uint_as_float(b & 0xFFFF0000u);
        g_w1t_hi[t] = __ushort_as_bfloat16((unsigned short)(b >> 16));
        g_w1t_lo[t] = __float2bfloat16(x - hf);
    } else {
        int t2 = t - DOUT * DIN;
        if (t2 < DOUT * DOUT) {             // W2^T: [n][k], n<128, k<128
            int n = t2 >> 7, k = t2 & 127;
            float x = W2[k * DOUT + n];
            uint32_t b = __float_as_uint(x);
            float hf = __uint_as_float(b & 0xFFFF0000u);
            g_w2t_hi[t2] = __ushort_as_bfloat16((unsigned short)(b >> 16));
            g_w2t_lo[t2] = __float2bfloat16(x - hf);
        }
    }
}

#if HAS_TCGEN05
// ---------------------------------------------------------------------------
// PTX helpers
// ---------------------------------------------------------------------------
__device__ __forceinline__ uint32_t smem_u32(const void* p) {
    uint32_t a;
    asm("{ .reg .u64 t; cvta.to.shared.u64 t, %1; cvt.u32.u64 %0, t; }"
        : "=r"(a) : "l"(p));
    return a;
}
__device__ __forceinline__ uint32_t elect_one() {
    uint32_t p;
    asm volatile("{ .reg .pred p; elect.sync _|p, 0xFFFFFFFF; selp.b32 %0,1,0,p; }"
                 : "=r"(p));
    return p;
}
#define TCG_ALLOC(sm, n)  asm volatile("tcgen05.alloc.cta_group::1.sync.aligned.shared::cta.b32 [%0], %1;" :: "r"(sm), "r"((uint32_t)(n)) : "memory")
#define TCG_DEALLOC(t, n) asm volatile("tcgen05.dealloc.cta_group::1.sync.aligned.b32 %0, %1;" :: "r"(t), "r"((uint32_t)(n)))
#define TCG_RELINQ()      asm volatile("tcgen05.relinquish_alloc_permit.cta_group::1.sync.aligned;")
#define TCG_COMMIT(mb)    asm volatile("tcgen05.commit.cta_group::1.mbarrier::arrive::one.shared::cluster.b64 [%0];" :: "r"(mb) : "memory")
#define TCG_WAIT_LD()     asm volatile("tcgen05.wait::ld.sync.aligned;" ::: "memory")
#define TCG_FENCE_BEFORE() asm volatile("tcgen05.fence::before_thread_sync;" ::: "memory")
#define TCG_FENCE_AFTER()  asm volatile("tcgen05.fence::after_thread_sync;" ::: "memory")
#define FENCE_ASYNC_SHARED() asm volatile("fence.proxy.async.shared::cta;" ::: "memory")
#define MBAR_INIT(mb, c)  asm volatile("mbarrier.init.shared.b64 [%0], %1;" :: "r"(mb), "r"((uint32_t)(c)) : "memory")
#define MBAR_INVAL(mb)    asm volatile("mbarrier.inval.shared.b64 [%0];" :: "r"(mb) : "memory")

__device__ __forceinline__ void mbar_wait(uint32_t mb, uint32_t parity) {
    asm volatile(
        "{\n\t.reg .pred P1;\n\t"
        "WAIT_LOOP_%=:\n\t"
        "mbarrier.try_wait.parity.acquire.cta.shared::cta.b64 P1, [%0], %1, 0x989680;\n\t"
        "@P1 bra.uni WAIT_DONE_%=;\n\t"
        "bra.uni WAIT_LOOP_%=;\n\t"
        "WAIT_DONE_%=:\n\t}"
        :: "r"(mb), "r"(parity) : "memory");
}

__device__ __forceinline__ void mma_ss(uint32_t d, uint64_t ad, uint64_t bd,
                                       uint32_t idesc, uint32_t en) {
    asm volatile(
        "{\n\t.reg .pred p;\n\tsetp.ne.u32 p, %4, 0;\n\t"
        "tcgen05.mma.cta_group::1.kind::f16 [%0], %1, %2, %3, {%5,%5,%5,%5}, p;\n\t}"
        :: "r"(d), "l"(ad), "l"(bd), "r"(idesc), "r"(en), "r"(0u) : "memory");
}

#define LDTM_X16(r, a) \
    asm volatile("tcgen05.ld.sync.aligned.32x32b.x16.b32 " \
        "{%0,%1,%2,%3,%4,%5,%6,%7,%8,%9,%10,%11,%12,%13,%14,%15}, [%16];" \
        : "=r"((r)[0]),"=r"((r)[1]),"=r"((r)[2]),"=r"((r)[3]), \
          "=r"((r)[4]),"=r"((r)[5]),"=r"((r)[6]),"=r"((r)[7]), \
          "=r"((r)[8]),"=r"((r)[9]),"=r"((r)[10]),"=r"((r)[11]), \
          "=r"((r)[12]),"=r"((r)[13]),"=r"((r)[14]),"=r"((r)[15]) : "r"(a))

#define LDTM_X32(r, a) \
    asm volatile("tcgen05.ld.sync.aligned.32x32b.x32.b32 " \
        "{%0,%1,%2,%3,%4,%5,%6,%7,%8,%9,%10,%11,%12,%13,%14,%15," \
        "%16,%17,%18,%19,%20,%21,%22,%23,%24,%25,%26,%27,%28,%29,%30,%31}, [%32];" \
        : "=r"((r)[0]),"=r"((r)[1]),"=r"((r)[2]),"=r"((r)[3]), \
          "=r"((r)[4]),"=r"((r)[5]),"=r"((r)[6]),"=r"((r)[7]), \
          "=r"((r)[8]),"=r"((r)[9]),"=r"((r)[10]),"=r"((r)[11]), \
          "=r"((r)[12]),"=r"((r)[13]),"=r"((r)[14]),"=r"((r)[15]), \
          "=r"((r)[16]),"=r"((r)[17]),"=r"((r)[18]),"=r"((r)[19]), \
          "=r"((r)[20]),"=r"((r)[21]),"=r"((r)[22]),"=r"((r)[23]), \
          "=r"((r)[24]),"=r"((r)[25]),"=r"((r)[26]),"=r"((r)[27]), \
          "=r"((r)[28]),"=r"((r)[29]),"=r"((r)[30]),"=r"((r)[31]) : "r"(a))

__device__ __forceinline__ uint64_t mk_desc(uint32_t addr) {
    return ((uint64_t)2 << 61) | ((uint64_t)1 << 46) | ((uint64_t)64 << 32) |
           ((uint64_t)1 << 16) | (uint64_t)((addr >> 4) & 0x3FFF);
}
#endif // HAS_TCGEN05

#define SWZ(o) ((o) ^ (((o) >> 3) & 0x70))

// Truncation split: hi = top-16-bits of fp32, lo = rn_bf16(x - hi)
__device__ __forceinline__ void split2(float x0, float x1, uint32_t& hi, uint32_t& lo) {
    uint32_t b0 = __float_as_uint(x0), b1 = __float_as_uint(x1);
    hi = __byte_perm(b0, b1, 0x7632);
    float l0 = x0 - __uint_as_float(b0 & 0xFFFF0000u);
    float l1 = x1 - __uint_as_float(b1 & 0xFFFF0000u);
    asm("cvt.rn.bf16x2.f32 %0, %1, %2;" : "=r"(lo) : "f"(l1), "f"(l0));
}

// 256-bit evict_last global load (8 floats)
__device__ __forceinline__ void ldg_evl8(const float* p, float* v) {
    uint64_t a, b, c, d;
    asm volatile("ld.global.nc.L2::evict_last.v4.b64 {%0,%1,%2,%3}, [%4];"
        : "=l"(a), "=l"(b), "=l"(c), "=l"(d) : "l"(p));
    v[0] = __uint_as_float((uint32_t)a); v[1] = __uint_as_float((uint32_t)(a >> 32));
    v[2] = __uint_as_float((uint32_t)b); v[3] = __uint_as_float((uint32_t)(b >> 32));
    v[4] = __uint_as_float((uint32_t)c); v[5] = __uint_as_float((uint32_t)(c >> 32));
    v[6] = __uint_as_float((uint32_t)d); v[7] = __uint_as_float((uint32_t)(d >> 32));
}

// ---------------------------------------------------------------------------
// MLP kernel: 128 rows/CTA, grid 1024, pipelined A conversion vs MMA.
// ---------------------------------------------------------------------------
__global__ __launch_bounds__(256, 2)
void mlp_kernel(const float* __restrict__ X,
                const float* __restrict__ W1,
                const float* __restrict__ b1,
                const float* __restrict__ W2,
                const float* __restrict__ b2)
{
    extern __shared__ char smem[];
#if HAS_TCGEN05
    const uint32_t sb  = smem_u32(smem);
    const int tid = threadIdx.x, wid = tid >> 5, lid = tid & 31;
    const long rowBase = (long)blockIdx.x * 128;

    float* b1s = (float*)(smem + SM_B1);
    float* b2s = (float*)(smem + SM_B2);

    if (wid == 0) { TCG_ALLOC(sb + 0, 256); TCG_RELINQ(); }
    if (tid == 0) { MBAR_INIT(sb + 8, 1); MBAR_INIT(sb + 16, 1); }
    if (tid < 128) { b1s[tid] = b1[tid]; b2s[tid] = b2[tid]; }
    __syncthreads();

    uint32_t tmem;
    asm volatile("ld.shared.b32 %0, [%1];" : "=r"(tmem) : "r"(sb + 0));

    const uint32_t idesc = (1u << 4) | (1u << 7) | (1u << 10) |
                           ((DOUT / 8) << 17) | ((128 / 16) << 24);
    const uint64_t adhiS[2] = { mk_desc(sb + SM_A0HI), mk_desc(sb + SM_A1HI) };
    const uint64_t adloS[2] = { mk_desc(sb + SM_A0LO), mk_desc(sb + SM_A1LO) };
    const uint64_t bdhi = mk_desc(sb + SM_BHI);
    const uint64_t bdlo = mk_desc(sb + SM_BLO);

    uint32_t ph0 = 0, ph1 = 0;

    // ================= GEMM1: 4 pipelined K-chunks of 64 =================
    for (int kb = 0; kb < 4; kb++) {
        const int st = kb & 1;
        const uint32_t aHI = st ? SM_A1HI : SM_A0HI;
        const uint32_t aLO = st ? SM_A1LO : SM_A0LO;
        // 1. convert A chunk kb -> stage st (overlaps MMA kb-1)
        const float* Xc = X + rowBase * DIN + kb * 64;
#pragma unroll
        for (int it = 0; it < 4; it++) {
            int f  = it * 256 + tid;
            int r  = f >> 3;
            int c8 = f & 7;
            const float4* src = (const float4*)(Xc + (size_t)r * DIN + c8 * 8);
            float4 va = src[0], vb = src[1];
            uint32_t h0, l0, h1, l1, h2, l2, h3, l3;
            split2(va.x, va.y, h0, l0);
            split2(va.z, va.w, h1, l1);
            split2(vb.x, vb.y, h2, l2);
            split2(vb.z, vb.w, h3, l3);
            uint32_t off = SWZ((uint32_t)(r * 128 + c8 * 16));
            *(uint4*)(smem + aHI + off) = make_uint4(h0, h1, h2, h3);
            *(uint4*)(smem + aLO + off) = make_uint4(l0, l1, l2, l3);
        }
        // 2. wait MMA kb-1 before overwriting the shared B buffer
        if (kb >= 1) {
            if ((kb - 1) & 1) { mbar_wait(sb + 16, ph1); ph1 ^= 1; }
            else              { mbar_wait(sb + 8,  ph0); ph0 ^= 1; }
        }
        // 3. load B chunk kb (W1^T hi+lo)
#pragma unroll
        for (int it = 0; it < 8; it++) {
            int f = it * 256 + tid;
            int g = f & 1023;
            int n = g >> 3, c16 = g & 7;
            const __nv_bfloat16* wsrc = (f < 1024) ? g_w1t_hi : g_w1t_lo;
            uint4 v = *(const uint4*)(wsrc + (size_t)n * DIN + kb * 64 + c16 * 8);
            uint32_t dst = ((f < 1024) ? SM_BHI : SM_BLO) + SWZ((uint32_t)(n * 128 + c16 * 16));
            *(uint4*)(smem + dst) = v;
        }
        __syncthreads();
        // 4. issue MMA kb (commit to mbar[st])
        if (wid == 0) {
            FENCE_ASYNC_SHARED();
            if (elect_one()) {
                uint64_t ah = adhiS[st], al = adloS[st];
#pragma unroll
                for (int ks = 0; ks < 4; ks++)
                    mma_ss(tmem, ah + ks * 2, bdhi + ks * 2, idesc, (kb > 0) || (ks > 0));
#pragma unroll
                for (int ks = 0; ks < 4; ks++)
                    mma_ss(tmem, ah + ks * 2, bdlo + ks * 2, idesc, 1);
#pragma unroll
                for (int ks = 0; ks < 4; ks++)
                    mma_ss(tmem, al + ks * 2, bdhi + ks * 2, idesc, 1);
                TCG_COMMIT(st ? (sb + 16) : (sb + 8));
            }
        }
    }
    // GEMM1 done when MMA3 completes (mbar1, 2nd phase)
    mbar_wait(sb + 16, ph1); ph1 ^= 1;
    TCG_FENCE_AFTER();

    // ================= GEMM2: 2 pipelined K-chunks of 64 =================
    for (int c2 = 0; c2 < 2; c2++) {
        const int st = c2 & 1;
        const uint32_t aHI = st ? SM_A1HI : SM_A0HI;
        const uint32_t aLO = st ? SM_A1LO : SM_A0LO;
        if (wid < 4) {
            // conversion warps: read D1, relu+bias, split -> stage st
            int row = wid * 32 + lid;
#pragma unroll
            for (int part = 0; part < 4; part++) {
                uint32_t r16[16];
                LDTM_X16(r16, tmem + c2 * 64 + part * 16);
                TCG_WAIT_LD();
#pragma unroll
                for (int grp = 0; grp < 2; grp++) {
                    uint32_t hs[4], ls[4];
#pragma unroll
                    for (int q = 0; q < 4; q++) {
                        int c = grp * 8 + q * 2;
                        float x0 = __uint_as_float(r16[c])     + b1s[c2 * 64 + part * 16 + c];
                        float x1 = __uint_as_float(r16[c + 1]) + b1s[c2 * 64 + part * 16 + c + 1];
                        x0 = fmaxf(x0, 0.f);
                        x1 = fmaxf(x1, 0.f);
                        split2(x0, x1, hs[q], ls[q]);
                    }
                    uint32_t off = SWZ((uint32_t)(row * 128 + (part * 16 + grp * 8) * 2));
                    *(uint4*)(smem + aHI + off) = make_uint4(hs[0], hs[1], hs[2], hs[3]);
                    *(uint4*)(smem + aLO + off) = make_uint4(ls[0], ls[1], ls[2], ls[3]);
                }
            }
        } else {
            // B-loading warps: wait GEMM2 MMA c2-1 (B buffer reuse), then load W2^T chunk
            if (c2 >= 1) { mbar_wait(sb + 8, ph0); }   // 3rd commit on mbar0
            int t2 = tid - 128;
#pragma unroll
            for (int it = 0; it < 16; it++) {
                int f = it * 128 + t2;
                int g = f & 1023;
                int n = g >> 3, c16 = g & 7;
                const __nv_bfloat16* wsrc = (f < 1024) ? g_w2t_hi : g_w2t_lo;
                uint4 v = *(const uint4*)(wsrc + (size_t)n * DOUT + c2 * 64 + c16 * 8);
                uint32_t dst = ((f < 1024) ? SM_BHI : SM_BLO) + SWZ((uint32_t)(n * 128 + c16 * 16));
                *(uint4*)(smem + dst) = v;
            }
        }
        __syncthreads();

        if (wid == 0) {
            FENCE_ASYNC_SHARED();
            if (elect_one()) {
                uint64_t ah = adhiS[st], al = adloS[st];
#pragma unroll
                for (int ks = 0; ks < 4; ks++)
                    mma_ss(tmem + 128, ah + ks * 2, bdhi + ks * 2, idesc, (c2 > 0) || (ks > 0));
#pragma unroll
                for (int ks = 0; ks < 4; ks++)
                    mma_ss(tmem + 128, ah + ks * 2, bdlo + ks * 2, idesc, 1);
#pragma unroll
                for (int ks = 0; ks < 4; ks++)
                    mma_ss(tmem + 128, al + ks * 2, bdhi + ks * 2, idesc, 1);
                TCG_COMMIT(st ? (sb + 16) : (sb + 8));
            }
        }
    }
    // GEMM2 done when its 2nd MMA completes (mbar1, 3rd phase = parity 0)
    mbar_wait(sb + 16, ph1);
    TCG_FENCE_AFTER();

    // ================= Epilogue: D2 + b2 -> g_h =================
    if (wid < 4) {
        int row = wid * 32 + lid;
        float* dst = g_h + (size_t)(rowBase + row) * DOUT;
#pragma unroll
        for (int grp = 0; grp < 4; grp++) {
            uint32_t r32[32];
            LDTM_X32(r32, tmem + 128 + grp * 32);
            TCG_WAIT_LD();
#pragma unroll
            for (int cb = 0; cb < 8; cb++) {
                float4 o;
                o.x = __uint_as_float(r32[cb * 4 + 0]) + b2s[grp * 32 + cb * 4 + 0];
                o.y = __uint_as_float(r32[cb * 4 + 1]) + b2s[grp * 32 + cb * 4 + 1];
                o.z = __uint_as_float(r32[cb * 4 + 2]) + b2s[grp * 32 + cb * 4 + 2];
                o.w = __uint_as_float(r32[cb * 4 + 3]) + b2s[grp * 32 + cb * 4 + 3];
                *(float4*)(dst + grp * 32 + cb * 4) = o;
            }
        }
        TCG_FENCE_BEFORE();
    }
    __syncthreads();
    if (tid == 0) { MBAR_INVAL(sb + 8); MBAR_INVAL(sb + 16); }
    __syncthreads();
    if (wid == 0) TCG_DEALLOC(tmem, 256);

#else  // ===================== fp32 FFMA fallback =====================
    float (*xs)[68]   = (float (*)[68])(smem);
    float (*ws)[128]  = (float (*)[128])(smem + 32 * 68 * 4);
    float (*h1T)[68]  = (float (*)[68])(smem + 32 * 68 * 4 + 32 * 128 * 4);

    const int tid = threadIdx.x;
    const int tr  = tid >> 5;
    const int tc  = tid & 31;

    for (int half = 0; half < 2; half++) {
        const long rowBase = (long)blockIdx.x * 128 + half * 64;
        float acc[8][4];
#pragma unroll
        for (int r = 0; r < 8; r++)
#pragma unroll
            for (int c = 0; c < 4; c++) acc[r][c] = 0.f;

        for (int kb = 0; kb < DIN; kb += 32) {
#pragma unroll
            for (int it = 0; it < 2; it++) {
                int f = tid + it * 256;
                int r  = f >> 3;
                int k4 = f & 7;
                float4 v = *(const float4*)(X + (rowBase + r) * DIN + kb + k4 * 4);
                xs[k4 * 4 + 0][r] = v.x;
                xs[k4 * 4 + 1][r] = v.y;
                xs[k4 * 4 + 2][r] = v.z;
                xs[k4 * 4 + 3][r] = v.w;
            }
#pragma unroll
            for (int it = 0; it < 4; it++) {
                int f  = tid + it * 256;
                int kr = f >> 5;
                int c4 = f & 31;
                *(float4*)&ws[kr][c4 * 4] =
                    *(const float4*)(W1 + (size_t)(kb + kr) * DOUT + c4 * 4);
            }
            __syncthreads();
#pragma unroll
            for (int kk = 0; kk < 32; kk++) {
                float4 xa = *(float4*)&xs[kk][tr * 8];
                float4 xb = *(float4*)&xs[kk][tr * 8 + 4];
                float4 w  = *(float4*)&ws[kk][tc * 4];
                float xr[8] = {xa.x, xa.y, xa.z, xa.w, xb.x, xb.y, xb.z, xb.w};
                float wr[4] = {w.x, w.y, w.z, w.w};
#pragma unroll
                for (int r = 0; r < 8; r++)
#pragma unroll
                    for (int c = 0; c < 4; c++)
                        acc[r][c] = fmaf(xr[r], wr[c], acc[r][c]);
            }
            __syncthreads();
        }
        {
            float bb[4];
#pragma unroll
            for (int c = 0; c < 4; c++) bb[c] = b1[tc * 4 + c];
#pragma unroll
            for (int r = 0; r < 8; r++)
#pragma unroll
                for (int c = 0; c < 4; c++) {
                    float v = acc[r][c] + bb[c];
                    h1T[tc * 4 + c][tr * 8 + r] = fmaxf(v, 0.f);
                    acc[r][c] = 0.f;
                }
        }
        __syncthreads();

        for (int kb = 0; kb < DOUT; kb += 32) {
#pragma unroll
            for (int it = 0; it < 4; it++) {
                int f  = tid + it * 256;
                int kr = f >> 5;
                int c4 = f & 31;
                *(float4*)&ws[kr][c4 * 4] =
                    *(const float4*)(W2 + (size_t)(kb + kr) * DOUT + c4 * 4);
            }
            __syncthreads();
#pragma unroll
            for (int kk = 0; kk < 32; kk++) {
                float4 xa = *(float4*)&h1T[kb + kk][tr * 8];
                float4 xb = *(float4*)&h1T[kb + kk][tr * 8 + 4];
                float4 w  = *(float4*)&ws[kk][tc * 4];
                float xr[8] = {xa.x, xa.y, xa.z, xa.w, xb.x, xb.y, xb.z, xb.w};
                float wr[4] = {w.x, w.y, w.z, w.w};
#pragma unroll
                for (int r = 0; r < 8; r++)
#pragma unroll
                    for (int c = 0; c < 4; c++)
                        acc[r][c] = fmaf(xr[r], wr[c], acc[r][c]);
            }
            __syncthreads();
        }
        {
            float bb[4];
#pragma unroll
            for (int c = 0; c < 4; c++) bb[c] = b2[tc * 4 + c];
#pragma unroll
            for (int r = 0; r < 8; r++) {
                float4 o;
                o.x = acc[r][0] + bb[0];
                o.y = acc[r][1] + bb[1];
                o.z = acc[r][2] + bb[2];
                o.w = acc[r][3] + bb[3];
                *(float4*)(g_h + (rowBase + tr * 8 + r) * DOUT + tc * 4) = o;
            }
        }
        __syncthreads();
    }
#endif
}

// ---------------------------------------------------------------------------
// Gather kernel: 16 lanes per (u,n) row, 8 floats (32B) per lane.
// g_h reads via 256-bit evict_last loads; up/out evict-first streaming.
// ---------------------------------------------------------------------------
__global__ __launch_bounds__(256)
void gather_add_kernel(const float* __restrict__ up,
                       const int*   __restrict__ idx,
                       float*       __restrict__ out)
{
    long t    = (long)blockIdx.x * blockDim.x + threadIdx.x;
    long row  = t >> 4;
    int  lane = threadIdx.x & 15;
    int  n    = (int)(row & 7);

    const int* ip = idx + row * 3;
    int i0 = __ldg(ip + 0);
    int i1 = __ldg(ip + 1);
    int i2 = __ldg(ip + 2);

    const float* p0 = g_h + (size_t)(i0 * NNm + n) * DOUT + lane * 8;
    const float* p1 = g_h + (size_t)(i1 * NNm + n) * DOUT + lane * 8;
    const float* p2 = g_h + (size_t)(i2 * NNm + n) * DOUT + lane * 8;

    float a[8], b[8], c[8];
    ldg_evl8(p0, a);
    ldg_evl8(p1, b);
    ldg_evl8(p2, c);

    const float4* upp = (const float4*)(up + row * DOUT + lane * 8);
    float4 u0 = __ldcs(upp);
    float4 u1 = __ldcs(upp + 1);

    const float inv3 = 1.0f / 3.0f;
    float4 o0, o1;
    o0.x = fmaf(a[0] + b[0] + c[0], inv3, u0.x);
    o0.y = fmaf(a[1] + b[1] + c[1], inv3, u0.y);
    o0.z = fmaf(a[2] + b[2] + c[2], inv3, u0.z);
    o0.w = fmaf(a[3] + b[3] + c[3], inv3, u0.w);
    o1.x = fmaf(a[4] + b[4] + c[4], inv3, u1.x);
    o1.y = fmaf(a[5] + b[5] + c[5], inv3, u1.y);
    o1.z = fmaf(a[6] + b[6] + c[6], inv3, u1.z);
    o1.w = fmaf(a[7] + b[7] + c[7], inv3, u1.w);

    float4* op = (float4*)(out + row * DOUT + lane * 8);
    __stcs(op,     o0);
    __stcs(op + 1, o1);
}

// ---------------------------------------------------------------------------
// Launch: inputs = down_features, up_features, idx, W1, b1, W2, b2
// ---------------------------------------------------------------------------
extern "C" void kernel_launch(void* const* d_in, const int* in_sizes, int n_in,
                              void* d_out, int out_size)
{
    const float* down = (const float*)d_in[0];
    const float* up   = (const float*)d_in[1];
    const int*   idx  = (const int*)  d_in[2];
    const float* W1   = (const float*)d_in[3];
    const float* b1   = (const float*)d_in[4];
    const float* W2   = (const float*)d_in[5];
    const float* b2   = (const float*)d_in[6];
    float* out = (float*)d_out;

    static int smem_set = 0;
    if (!smem_set) {
        cudaFuncSetAttribute(mlp_kernel,
                             cudaFuncAttributeMaxDynamicSharedMemorySize, SMEM_TOTAL);
        smem_set = 1;
    }

    // 1. Split weights into bf16 hi/lo
    wsplit_kernel<<<192, 256>>>(W1, W2);

    // 2. MLP -> g_h (pipelined: A-conversion overlaps MMA)
    mlp_kernel<<<M_ROWS / 128, 256, SMEM_TOTAL>>>(down, W1, b1, W2, b2);

    // 3. Gather + mean + add
    gather_add_kernel<<<(int)(OUT_ROWS * 16 / 256), 256>>>(up, idx, out);
}

// round 9
// speedup vs baseline: 1.1328x; 1.1328x over previous
#include <cuda_runtime.h>
#include <cuda_bf16.h>
#include <cstdint>

// Problem constants
#define LDm   16384
#define LUm   65536
#define NNm   8
#define DIN   256
#define DOUT  128
#define M_ROWS (LDm * NNm)            // 131072 MLP rows
#define OUT_ROWS ((long)LUm * NNm)    // 524288 output rows

// Arch-specific (sm_103a/sm_100a) pass?
#if defined(__CUDA_ARCH__) && (defined(__CUDA_ARCH_FEAT_SM103_ALL) || \
    defined(__CUDA_ARCH_FEAT_SM100_ALL) || \
    (defined(__CUDA_ARCH_SPECIFIC__) && (__CUDA_ARCH_SPECIFIC__ >= 1000)))
#define HAS_TCGEN05 1
#else
#define HAS_TCGEN05 0
#endif

// Scratch: h = relu(x@W1+b1)@W2+b2  [LD, N, D_OUT] in bf16 (32 MB)
__device__ __align__(128) __nv_bfloat16 g_h[(size_t)M_ROWS * DOUT];
// Precomputed bf16 hi/lo splits of W1^T, W2^T (B operands, N x K, K-major)
__device__ __align__(16) __nv_bfloat16 g_w1t_hi[DOUT * DIN];
__device__ __align__(16) __nv_bfloat16 g_w1t_lo[DOUT * DIN];
__device__ __align__(16) __nv_bfloat16 g_w2t_hi[DOUT * DOUT];
__device__ __align__(16) __nv_bfloat16 g_w2t_lo[DOUT * DOUT];

#define SMEM_TOTAL 67584

// ---------------------------------------------------------------------------
// Pre-kernel: split W1^T / W2^T into bf16 hi/lo
// ---------------------------------------------------------------------------
__global__ void wsplit_kernel(const float* __restrict__ W1,
                              const float* __restrict__ W2)
{
    int t = blockIdx.x * blockDim.x + threadIdx.x;
    if (t < DOUT * DIN) {                   // W1^T: [n][k], n<128, k<256
        int n = t >> 8, k = t & 255;
        float x = W1[k * DOUT + n];
        uint32_t b = __float_as_uint(x);
        float hf = __uint_as_float(b & 0xFFFF0000u);
        g_w1t_hi[t] = __ushort_as_bfloat16((unsigned short)(b >> 16));
        g_w1t_lo[t] = __float2bfloat16(x - hf);
    } else {
        int t2 = t - DOUT * DIN;
        if (t2 < DOUT * DOUT) {             // W2^T: [n][k], n<128, k<128
            int n = t2 >> 7, k = t2 & 127;
            float x = W2[k * DOUT + n];
            uint32_t b = __float_as_uint(x);
            float hf = __uint_as_float(b & 0xFFFF0000u);
            g_w2t_hi[t2] = __ushort_as_bfloat16((unsigned short)(b >> 16));
            g_w2t_lo[t2] = __float2bfloat16(x - hf);
        }
    }
}

#if HAS_TCGEN05
// ---------------------------------------------------------------------------
// PTX helpers
// ---------------------------------------------------------------------------
__device__ __forceinline__ uint32_t smem_u32(const void* p) {
    uint32_t a;
    asm("{ .reg .u64 t; cvta.to.shared.u64 t, %1; cvt.u32.u64 %0, t; }"
        : "=r"(a) : "l"(p));
    return a;
}
__device__ __forceinline__ uint32_t elect_one() {
    uint32_t p;
    asm volatile("{ .reg .pred p; elect.sync _|p, 0xFFFFFFFF; selp.b32 %0,1,0,p; }"
                 : "=r"(p));
    return p;
}
#define TCG_ALLOC(sm, n)  asm volatile("tcgen05.alloc.cta_group::1.sync.aligned.shared::cta.b32 [%0], %1;" :: "r"(sm), "r"((uint32_t)(n)) : "memory")
#define TCG_DEALLOC(t, n) asm volatile("tcgen05.dealloc.cta_group::1.sync.aligned.b32 %0, %1;" :: "r"(t), "r"((uint32_t)(n)))
#define TCG_RELINQ()      asm volatile("tcgen05.relinquish_alloc_permit.cta_group::1.sync.aligned;")
#define TCG_COMMIT(mb)    asm volatile("tcgen05.commit.cta_group::1.mbarrier::arrive::one.shared::cluster.b64 [%0];" :: "r"(mb) : "memory")
#define TCG_WAIT_LD()     asm volatile("tcgen05.wait::ld.sync.aligned;" ::: "memory")
#define TCG_FENCE_BEFORE() asm volatile("tcgen05.fence::before_thread_sync;" ::: "memory")
#define TCG_FENCE_AFTER()  asm volatile("tcgen05.fence::after_thread_sync;" ::: "memory")
#define FENCE_ASYNC_SHARED() asm volatile("fence.proxy.async.shared::cta;" ::: "memory")
#define MBAR_INIT(mb, c)  asm volatile("mbarrier.init.shared.b64 [%0], %1;" :: "r"(mb), "r"((uint32_t)(c)) : "memory")
#define MBAR_INVAL(mb)    asm volatile("mbarrier.inval.shared.b64 [%0];" :: "r"(mb) : "memory")

__device__ __forceinline__ void mbar_wait(uint32_t mb, uint32_t parity) {
    asm volatile(
        "{\n\t.reg .pred P1;\n\t"
        "WAIT_LOOP_%=:\n\t"
        "mbarrier.try_wait.parity.acquire.cta.shared::cta.b64 P1, [%0], %1, 0x989680;\n\t"
        "@P1 bra.uni WAIT_DONE_%=;\n\t"
        "bra.uni WAIT_LOOP_%=;\n\t"
        "WAIT_DONE_%=:\n\t}"
        :: "r"(mb), "r"(parity) : "memory");
}

__device__ __forceinline__ void mma_ss(uint32_t d, uint64_t ad, uint64_t bd,
                                       uint32_t idesc, uint32_t en) {
    asm volatile(
        "{\n\t.reg .pred p;\n\tsetp.ne.u32 p, %4, 0;\n\t"
        "tcgen05.mma.cta_group::1.kind::f16 [%0], %1, %2, %3, {%5,%5,%5,%5}, p;\n\t}"
        :: "r"(d), "l"(ad), "l"(bd), "r"(idesc), "r"(en), "r"(0u) : "memory");
}

#define LDTM_X16(r, a) \
    asm volatile("tcgen05.ld.sync.aligned.32x32b.x16.b32 " \
        "{%0,%1,%2,%3,%4,%5,%6,%7,%8,%9,%10,%11,%12,%13,%14,%15}, [%16];" \
        : "=r"((r)[0]),"=r"((r)[1]),"=r"((r)[2]),"=r"((r)[3]), \
          "=r"((r)[4]),"=r"((r)[5]),"=r"((r)[6]),"=r"((r)[7]), \
          "=r"((r)[8]),"=r"((r)[9]),"=r"((r)[10]),"=r"((r)[11]), \
          "=r"((r)[12]),"=r"((r)[13]),"=r"((r)[14]),"=r"((r)[15]) : "r"(a))

#define LDTM_X32(r, a) \
    asm volatile("tcgen05.ld.sync.aligned.32x32b.x32.b32 " \
        "{%0,%1,%2,%3,%4,%5,%6,%7,%8,%9,%10,%11,%12,%13,%14,%15," \
        "%16,%17,%18,%19,%20,%21,%22,%23,%24,%25,%26,%27,%28,%29,%30,%31}, [%32];" \
        : "=r"((r)[0]),"=r"((r)[1]),"=r"((r)[2]),"=r"((r)[3]), \
          "=r"((r)[4]),"=r"((r)[5]),"=r"((r)[6]),"=r"((r)[7]), \
          "=r"((r)[8]),"=r"((r)[9]),"=r"((r)[10]),"=r"((r)[11]), \
          "=r"((r)[12]),"=r"((r)[13]),"=r"((r)[14]),"=r"((r)[15]), \
          "=r"((r)[16]),"=r"((r)[17]),"=r"((r)[18]),"=r"((r)[19]), \
          "=r"((r)[20]),"=r"((r)[21]),"=r"((r)[22]),"=r"((r)[23]), \
          "=r"((r)[24]),"=r"((r)[25]),"=r"((r)[26]),"=r"((r)[27]), \
          "=r"((r)[28]),"=r"((r)[29]),"=r"((r)[30]),"=r"((r)[31]) : "r"(a))

__device__ __forceinline__ uint64_t mk_desc(uint32_t addr) {
    return ((uint64_t)2 << 61) | ((uint64_t)1 << 46) | ((uint64_t)64 << 32) |
           ((uint64_t)1 << 16) | (uint64_t)((addr >> 4) & 0x3FFF);
}
#endif // HAS_TCGEN05

#define SWZ(o) ((o) ^ (((o) >> 3) & 0x70))

// Truncation split: hi = top-16-bits of fp32, lo = rn_bf16(x - hi)
__device__ __forceinline__ void split2(float x0, float x1, uint32_t& hi, uint32_t& lo) {
    uint32_t b0 = __float_as_uint(x0), b1 = __float_as_uint(x1);
    hi = __byte_perm(b0, b1, 0x7632);
    float l0 = x0 - __uint_as_float(b0 & 0xFFFF0000u);
    float l1 = x1 - __uint_as_float(b1 & 0xFFFF0000u);
    asm("cvt.rn.bf16x2.f32 %0, %1, %2;" : "=r"(lo) : "f"(l1), "f"(l0));
}

// pack two fp32 into bf16x2 word (lo half = x0)
__device__ __forceinline__ uint32_t pack_bf16x2(float x0, float x1) {
    uint32_t w;
    asm("cvt.rn.bf16x2.f32 %0, %1, %2;" : "=r"(w) : "f"(x1), "f"(x0));
    return w;
}

// 256-bit evict_last global load: 4 x u64 (= 16 bf16)
__device__ __forceinline__ void ldg_evl4x64(const void* p, uint64_t* v) {
    asm volatile("ld.global.nc.L2::evict_last.v4.b64 {%0,%1,%2,%3}, [%4];"
        : "=l"(v[0]), "=l"(v[1]), "=l"(v[2]), "=l"(v[3]) : "l"(p));
}
// 256-bit evict_last global store: 4 x u64
__device__ __forceinline__ void stg_evl4x64(void* p, const uint64_t* v) {
    asm volatile("st.global.L2::evict_last.v4.b64 [%0], {%1,%2,%3,%4};"
        :: "l"(p), "l"(v[0]), "l"(v[1]), "l"(v[2]), "l"(v[3]) : "memory");
}

// ---------------------------------------------------------------------------
// MLP kernel — R3/R7 structure (measured 71us): 128 rows/CTA, grid 1024.
// Epilogue now writes bf16 g_h.
// ---------------------------------------------------------------------------
__global__ __launch_bounds__(256, 2)
void mlp_kernel(const float* __restrict__ X,
                const float* __restrict__ W1,
                const float* __restrict__ b1,
                const float* __restrict__ W2,
                const float* __restrict__ b2)
{
    extern __shared__ char smem[];
#if HAS_TCGEN05
#define SM_AHI 1024
#define SM_ALO 17408
#define SM_BHI 33792
#define SM_BLO 50176
#define SM_B1  66560
#define SM_B2  67072
    const uint32_t sb  = smem_u32(smem);
    const int tid = threadIdx.x, wid = tid >> 5, lid = tid & 31;
    const long rowBase = (long)blockIdx.x * 128;

    float* b1s = (float*)(smem + SM_B1);
    float* b2s = (float*)(smem + SM_B2);

    if (wid == 0) { TCG_ALLOC(sb + 0, 256); TCG_RELINQ(); }
    if (tid == 0) MBAR_INIT(sb + 8, 1);
    if (tid < 128) { b1s[tid] = b1[tid]; b2s[tid] = b2[tid]; }
    __syncthreads();

    uint32_t tmem;
    asm volatile("ld.shared.b32 %0, [%1];" : "=r"(tmem) : "r"(sb + 0));

    const uint32_t idesc = (1u << 4) | (1u << 7) | (1u << 10) |
                           ((DOUT / 8) << 17) | ((128 / 16) << 24);
    const uint64_t adhi = mk_desc(sb + SM_AHI);
    const uint64_t adlo = mk_desc(sb + SM_ALO);
    const uint64_t bdhi = mk_desc(sb + SM_BHI);
    const uint64_t bdlo = mk_desc(sb + SM_BLO);

    uint32_t parity = 0;

    // ================= GEMM1: 4 K-chunks of 64 =================
    for (int kb = 0; kb < 4; kb++) {
        const float* Xc = X + rowBase * DIN + kb * 64;
#pragma unroll
        for (int it = 0; it < 4; it++) {
            int f  = it * 256 + tid;
            int r  = f >> 3;
            int c8 = f & 7;
            const float4* src = (const float4*)(Xc + (size_t)r * DIN + c8 * 8);
            float4 va = src[0], vb = src[1];
            uint32_t h0, l0, h1, l1, h2, l2, h3, l3;
            split2(va.x, va.y, h0, l0);
            split2(va.z, va.w, h1, l1);
            split2(vb.x, vb.y, h2, l2);
            split2(vb.z, vb.w, h3, l3);
            uint32_t off = SWZ((uint32_t)(r * 128 + c8 * 16));
            *(uint4*)(smem + SM_AHI + off) = make_uint4(h0, h1, h2, h3);
            *(uint4*)(smem + SM_ALO + off) = make_uint4(l0, l1, l2, l3);
        }
#pragma unroll
        for (int it = 0; it < 8; it++) {
            int f = it * 256 + tid;
            int g = f & 1023;
            int n = g >> 3, c16 = g & 7;
            const __nv_bfloat16* wsrc = (f < 1024) ? g_w1t_hi : g_w1t_lo;
            uint4 v = *(const uint4*)(wsrc + (size_t)n * DIN + kb * 64 + c16 * 8);
            uint32_t dst = ((f < 1024) ? SM_BHI : SM_BLO) + SWZ((uint32_t)(n * 128 + c16 * 16));
            *(uint4*)(smem + dst) = v;
        }
        __syncthreads();

        if (wid == 0) {
            FENCE_ASYNC_SHARED();
            if (elect_one()) {
#pragma unroll
                for (int ks = 0; ks < 4; ks++)
                    mma_ss(tmem, adhi + ks * 2, bdhi + ks * 2, idesc, (kb > 0) || (ks > 0));
#pragma unroll
                for (int ks = 0; ks < 4; ks++)
                    mma_ss(tmem, adhi + ks * 2, bdlo + ks * 2, idesc, 1);
#pragma unroll
                for (int ks = 0; ks < 4; ks++)
                    mma_ss(tmem, adlo + ks * 2, bdhi + ks * 2, idesc, 1);
                TCG_COMMIT(sb + 8);
            }
        }
        mbar_wait(sb + 8, parity); parity ^= 1;
        TCG_FENCE_AFTER();
        __syncthreads();
    }

    // ================= GEMM2: 2 K-chunks of 64 =================
    for (int c2 = 0; c2 < 2; c2++) {
        if (wid < 4) {
            int row = wid * 32 + lid;
#pragma unroll
            for (int part = 0; part < 4; part++) {
                uint32_t r16[16];
                LDTM_X16(r16, tmem + c2 * 64 + part * 16);
                TCG_WAIT_LD();
#pragma unroll
                for (int grp = 0; grp < 2; grp++) {
                    uint32_t hs[4], ls[4];
#pragma unroll
                    for (int q = 0; q < 4; q++) {
                        int c = grp * 8 + q * 2;
                        float x0 = __uint_as_float(r16[c])     + b1s[c2 * 64 + part * 16 + c];
                        float x1 = __uint_as_float(r16[c + 1]) + b1s[c2 * 64 + part * 16 + c + 1];
                        x0 = fmaxf(x0, 0.f);
                        x1 = fmaxf(x1, 0.f);
                        split2(x0, x1, hs[q], ls[q]);
                    }
                    uint32_t off = SWZ((uint32_t)(row * 128 + (part * 16 + grp * 8) * 2));
                    *(uint4*)(smem + SM_AHI + off) = make_uint4(hs[0], hs[1], hs[2], hs[3]);
                    *(uint4*)(smem + SM_ALO + off) = make_uint4(ls[0], ls[1], ls[2], ls[3]);
                }
            }
        } else {
            int t2 = tid - 128;
#pragma unroll
            for (int it = 0; it < 16; it++) {
                int f = it * 128 + t2;
                int g = f & 1023;
                int n = g >> 3, c16 = g & 7;
                const __nv_bfloat16* wsrc = (f < 1024) ? g_w2t_hi : g_w2t_lo;
                uint4 v = *(const uint4*)(wsrc + (size_t)n * DOUT + c2 * 64 + c16 * 8);
                uint32_t dst = ((f < 1024) ? SM_BHI : SM_BLO) + SWZ((uint32_t)(n * 128 + c16 * 16));
                *(uint4*)(smem + dst) = v;
            }
        }
        __syncthreads();

        if (wid == 0) {
            FENCE_ASYNC_SHARED();
            if (elect_one()) {
#pragma unroll
                for (int ks = 0; ks < 4; ks++)
                    mma_ss(tmem + 128, adhi + ks * 2, bdhi + ks * 2, idesc, (c2 > 0) || (ks > 0));
#pragma unroll
                for (int ks = 0; ks < 4; ks++)
                    mma_ss(tmem + 128, adhi + ks * 2, bdlo + ks * 2, idesc, 1);
#pragma unroll
                for (int ks = 0; ks < 4; ks++)
                    mma_ss(tmem + 128, adlo + ks * 2, bdhi + ks * 2, idesc, 1);
                TCG_COMMIT(sb + 8);
            }
        }
        mbar_wait(sb + 8, parity); parity ^= 1;
        TCG_FENCE_AFTER();
        __syncthreads();
    }

    // ================= Epilogue: bf16(D2 + b2) -> g_h =================
    if (wid < 4) {
        int row = wid * 32 + lid;
        __nv_bfloat16* dst = g_h + (size_t)(rowBase + row) * DOUT;
#pragma unroll
        for (int grp = 0; grp < 4; grp++) {
            uint32_t r32[32];
            LDTM_X32(r32, tmem + 128 + grp * 32);
            TCG_WAIT_LD();
            // 32 floats -> 16 bf16x2 words -> 2 x 32B stores
            uint64_t w64[8];
#pragma unroll
            for (int q = 0; q < 8; q++) {
                float x0 = __uint_as_float(r32[q * 4 + 0]) + b2s[grp * 32 + q * 4 + 0];
                float x1 = __uint_as_float(r32[q * 4 + 1]) + b2s[grp * 32 + q * 4 + 1];
                float x2 = __uint_as_float(r32[q * 4 + 2]) + b2s[grp * 32 + q * 4 + 2];
                float x3 = __uint_as_float(r32[q * 4 + 3]) + b2s[grp * 32 + q * 4 + 3];
                uint32_t wlo = pack_bf16x2(x0, x1);
                uint32_t whi = pack_bf16x2(x2, x3);
                w64[q] = (uint64_t)wlo | ((uint64_t)whi << 32);
            }
            stg_evl4x64(dst + grp * 32,      w64);
            stg_evl4x64(dst + grp * 32 + 16, w64 + 4);
        }
        TCG_FENCE_BEFORE();
    }
    __syncthreads();
    if (tid == 0) MBAR_INVAL(sb + 8);
    __syncthreads();
    if (wid == 0) TCG_DEALLOC(tmem, 256);

#else  // ===================== fp32 FFMA fallback =====================
    float (*xs)[68]   = (float (*)[68])(smem);
    float (*ws)[128]  = (float (*)[128])(smem + 32 * 68 * 4);
    float (*h1T)[68]  = (float (*)[68])(smem + 32 * 68 * 4 + 32 * 128 * 4);

    const int tid = threadIdx.x;
    const int tr  = tid >> 5;
    const int tc  = tid & 31;

    for (int half = 0; half < 2; half++) {
        const long rowBase = (long)blockIdx.x * 128 + half * 64;
        float acc[8][4];
#pragma unroll
        for (int r = 0; r < 8; r++)
#pragma unroll
            for (int c = 0; c < 4; c++) acc[r][c] = 0.f;

        for (int kb = 0; kb < DIN; kb += 32) {
#pragma unroll
            for (int it = 0; it < 2; it++) {
                int f = tid + it * 256;
                int r  = f >> 3;
                int k4 = f & 7;
                float4 v = *(const float4*)(X + (rowBase + r) * DIN + kb + k4 * 4);
                xs[k4 * 4 + 0][r] = v.x;
                xs[k4 * 4 + 1][r] = v.y;
                xs[k4 * 4 + 2][r] = v.z;
                xs[k4 * 4 + 3][r] = v.w;
            }
#pragma unroll
            for (int it = 0; it < 4; it++) {
                int f  = tid + it * 256;
                int kr = f >> 5;
                int c4 = f & 31;
                *(float4*)&ws[kr][c4 * 4] =
                    *(const float4*)(W1 + (size_t)(kb + kr) * DOUT + c4 * 4);
            }
            __syncthreads();
#pragma unroll
            for (int kk = 0; kk < 32; kk++) {
                float4 xa = *(float4*)&xs[kk][tr * 8];
                float4 xb = *(float4*)&xs[kk][tr * 8 + 4];
                float4 w  = *(float4*)&ws[kk][tc * 4];
                float xr[8] = {xa.x, xa.y, xa.z, xa.w, xb.x, xb.y, xb.z, xb.w};
                float wr[4] = {w.x, w.y, w.z, w.w};
#pragma unroll
                for (int r = 0; r < 8; r++)
#pragma unroll
                    for (int c = 0; c < 4; c++)
                        acc[r][c] = fmaf(xr[r], wr[c], acc[r][c]);
            }
            __syncthreads();
        }
        {
            float bb[4];
#pragma unroll
            for (int c = 0; c < 4; c++) bb[c] = b1[tc * 4 + c];
#pragma unroll
            for (int r = 0; r < 8; r++)
#pragma unroll
                for (int c = 0; c < 4; c++) {
                    float v = acc[r][c] + bb[c];
                    h1T[tc * 4 + c][tr * 8 + r] = fmaxf(v, 0.f);
                    acc[r][c] = 0.f;
                }
        }
        __syncthreads();

        for (int kb = 0; kb < DOUT; kb += 32) {
#pragma unroll
            for (int it = 0; it < 4; it++) {
                int f  = tid + it * 256;
                int kr = f >> 5;
                int c4 = f & 31;
                *(float4*)&ws[kr][c4 * 4] =
                    *(const float4*)(W2 + (size_t)(kb + kr) * DOUT + c4 * 4);
            }
            __syncthreads();
#pragma unroll
            for (int kk = 0; kk < 32; kk++) {
                float4 xa = *(float4*)&h1T[kb + kk][tr * 8];
                float4 xb = *(float4*)&h1T[kb + kk][tr * 8 + 4];
                float4 w  = *(float4*)&ws[kk][tc * 4];
                float xr[8] = {xa.x, xa.y, xa.z, xa.w, xb.x, xb.y, xb.z, xb.w};
                float wr[4] = {w.x, w.y, w.z, w.w};
#pragma unroll
                for (int r = 0; r < 8; r++)
#pragma unroll
                    for (int c = 0; c < 4; c++)
                        acc[r][c] = fmaf(xr[r], wr[c], acc[r][c]);
            }
            __syncthreads();
        }
        {
            float bb[4];
#pragma unroll
            for (int c = 0; c < 4; c++) bb[c] = b2[tc * 4 + c];
#pragma unroll
            for (int r = 0; r < 8; r++) {
                float x0 = acc[r][0] + bb[0];
                float x1 = acc[r][1] + bb[1];
                float x2 = acc[r][2] + bb[2];
                float x3 = acc[r][3] + bb[3];
                uint2 o;
                o.x = pack_bf16x2(x0, x1);
                o.y = pack_bf16x2(x2, x3);
                *(uint2*)(g_h + (rowBase + tr * 8 + r) * DOUT + tc * 4) = o;
            }
        }
        __syncthreads();
    }
#endif
}

// ---------------------------------------------------------------------------
// Gather kernel: 8 lanes per (u,n) row, 16 bf16 (32B) per lane.
// g_h reads via 256-bit evict_last loads; up/out evict-first streaming.
// ---------------------------------------------------------------------------
__global__ __launch_bounds__(256)
void gather_add_kernel(const float* __restrict__ up,
                       const int*   __restrict__ idx,
                       float*       __restrict__ out)
{
    long t    = (long)blockIdx.x * blockDim.x + threadIdx.x;
    long row  = t >> 3;                 // (u*8 + n), < 524288
    int  lane = threadIdx.x & 7;        // 16-bf16 chunk id
    int  n    = (int)(row & 7);

    const int* ip = idx + row * 3;
    int i0 = __ldg(ip + 0);
    int i1 = __ldg(ip + 1);
    int i2 = __ldg(ip + 2);

    const __nv_bfloat16* p0 = g_h + (size_t)(i0 * NNm + n) * DOUT + lane * 16;
    const __nv_bfloat16* p1 = g_h + (size_t)(i1 * NNm + n) * DOUT + lane * 16;
    const __nv_bfloat16* p2 = g_h + (size_t)(i2 * NNm + n) * DOUT + lane * 16;

    uint64_t ga[4], gb[4], gc[4];
    ldg_evl4x64(p0, ga);
    ldg_evl4x64(p1, gb);
    ldg_evl4x64(p2, gc);

    const float4* upp = (const float4*)(up + row * DOUT + lane * 16);
    float4 u[4];
    u[0] = __ldcs(upp + 0);
    u[1] = __ldcs(upp + 1);
    u[2] = __ldcs(upp + 2);
    u[3] = __ldcs(upp + 3);

    const float inv3 = 1.0f / 3.0f;
    float4 o[4];
    float* uo = (float*)u;
    float* oo = (float*)o;
#pragma unroll
    for (int q = 0; q < 4; q++) {          // each u64 = 4 bf16
#pragma unroll
        for (int hw = 0; hw < 2; hw++) {   // each u32 word = 2 bf16
            uint32_t wa = (uint32_t)(ga[q] >> (hw * 32));
            uint32_t wb = (uint32_t)(gb[q] >> (hw * 32));
            uint32_t wc = (uint32_t)(gc[q] >> (hw * 32));
            float a0 = __uint_as_float(wa << 16), a1 = __uint_as_float(wa & 0xFFFF0000u);
            float b0 = __uint_as_float(wb << 16), b1 = __uint_as_float(wb & 0xFFFF0000u);
            float c0 = __uint_as_float(wc << 16), c1 = __uint_as_float(wc & 0xFFFF0000u);
            int e = q * 4 + hw * 2;
            oo[e + 0] = fmaf(a0 + b0 + c0, inv3, uo[e + 0]);
            oo[e + 1] = fmaf(a1 + b1 + c1, inv3, uo[e + 1]);
        }
    }

    float4* op = (float4*)(out + row * DOUT + lane * 16);
    __stcs(op + 0, o[0]);
    __stcs(op + 1, o[1]);
    __stcs(op + 2, o[2]);
    __stcs(op + 3, o[3]);
}

// ---------------------------------------------------------------------------
// Launch: inputs = down_features, up_features, idx, W1, b1, W2, b2
// ---------------------------------------------------------------------------
extern "C" void kernel_launch(void* const* d_in, const int* in_sizes, int n_in,
                              void* d_out, int out_size)
{
    const float* down = (const float*)d_in[0];
    const float* up   = (const float*)d_in[1];
    const int*   idx  = (const int*)  d_in[2];
    const float* W1   = (const float*)d_in[3];
    const float* b1   = (const float*)d_in[4];
    const float* W2   = (const float*)d_in[5];
    const float* b2   = (const float*)d_in[6];
    float* out = (float*)d_out;

    static int smem_set = 0;
    if (!smem_set) {
        cudaFuncSetAttribute(mlp_kernel,
                             cudaFuncAttributeMaxDynamicSharedMemorySize, SMEM_TOTAL);
        smem_set = 1;
    }

    // 1. Split weights into bf16 hi/lo
    wsplit_kernel<<<192, 256>>>(W1, W2);

    // 2. MLP -> g_h bf16 (R3 shape: 128 rows per CTA, grid 1024)
    mlp_kernel<<<M_ROWS / 128, 256, SMEM_TOTAL>>>(down, W1, b1, W2, b2);

    // 3. Gather + mean + add (8 lanes x 32B bf16 per row)
    gather_add_kernel<<<(int)(OUT_ROWS * 8 / 256), 256>>>(up, idx, out);
}

// round 10
// speedup vs baseline: 1.1974x; 1.0570x over previous
#include <cuda_runtime.h>
#include <cuda_bf16.h>
#include <cstdint>

// Problem constants
#define LDm   16384
#define LUm   65536
#define NNm   8
#define DIN   256
#define DOUT  128
#define M_ROWS (LDm * NNm)            // 131072 MLP rows
#define OUT_ROWS ((long)LUm * NNm)    // 524288 output rows

// Arch-specific (sm_103a/sm_100a) pass?
#if defined(__CUDA_ARCH__) && (defined(__CUDA_ARCH_FEAT_SM103_ALL) || \
    defined(__CUDA_ARCH_FEAT_SM100_ALL) || \
    (defined(__CUDA_ARCH_SPECIFIC__) && (__CUDA_ARCH_SPECIFIC__ >= 1000)))
#define HAS_TCGEN05 1
#else
#define HAS_TCGEN05 0
#endif

// Scratch: h = relu(x@W1+b1)@W2+b2  [LD, N, D_OUT] in bf16 (32 MB)
__device__ __align__(128) __nv_bfloat16 g_h[(size_t)M_ROWS * DOUT];
// Precomputed bf16 hi/lo splits of W1^T, W2^T (B operands, N x K, K-major)
__device__ __align__(16) __nv_bfloat16 g_w1t_hi[DOUT * DIN];
__device__ __align__(16) __nv_bfloat16 g_w1t_lo[DOUT * DIN];
__device__ __align__(16) __nv_bfloat16 g_w2t_hi[DOUT * DOUT];
__device__ __align__(16) __nv_bfloat16 g_w2t_lo[DOUT * DOUT];

#define SMEM_TOTAL 67584

// ---------------------------------------------------------------------------
// Pre-kernel: split W1^T / W2^T into bf16 hi/lo
// ---------------------------------------------------------------------------
__global__ void wsplit_kernel(const float* __restrict__ W1,
                              const float* __restrict__ W2)
{
    int t = blockIdx.x * blockDim.x + threadIdx.x;
    if (t < DOUT * DIN) {                   // W1^T: [n][k], n<128, k<256
        int n = t >> 8, k = t & 255;
        float x = W1[k * DOUT + n];
        uint32_t b = __float_as_uint(x);
        float hf = __uint_as_float(b & 0xFFFF0000u);
        g_w1t_hi[t] = __ushort_as_bfloat16((unsigned short)(b >> 16));
        g_w1t_lo[t] = __float2bfloat16(x - hf);
    } else {
        int t2 = t - DOUT * DIN;
        if (t2 < DOUT * DOUT) {             // W2^T: [n][k], n<128, k<128
            int n = t2 >> 7, k = t2 & 127;
            float x = W2[k * DOUT + n];
            uint32_t b = __float_as_uint(x);
            float hf = __uint_as_float(b & 0xFFFF0000u);
            g_w2t_hi[t2] = __ushort_as_bfloat16((unsigned short)(b >> 16));
            g_w2t_lo[t2] = __float2bfloat16(x - hf);
        }
    }
}

#if HAS_TCGEN05
// ---------------------------------------------------------------------------
// PTX helpers
// ---------------------------------------------------------------------------
__device__ __forceinline__ uint32_t smem_u32(const void* p) {
    uint32_t a;
    asm("{ .reg .u64 t; cvta.to.shared.u64 t, %1; cvt.u32.u64 %0, t; }"
        : "=r"(a) : "l"(p));
    return a;
}
__device__ __forceinline__ uint32_t elect_one() {
    uint32_t p;
    asm volatile("{ .reg .pred p; elect.sync _|p, 0xFFFFFFFF; selp.b32 %0,1,0,p; }"
                 : "=r"(p));
    return p;
}
#define TCG_ALLOC(sm, n)  asm volatile("tcgen05.alloc.cta_group::1.sync.aligned.shared::cta.b32 [%0], %1;" :: "r"(sm), "r"((uint32_t)(n)) : "memory")
#define TCG_DEALLOC(t, n) asm volatile("tcgen05.dealloc.cta_group::1.sync.aligned.b32 %0, %1;" :: "r"(t), "r"((uint32_t)(n)))
#define TCG_RELINQ()      asm volatile("tcgen05.relinquish_alloc_permit.cta_group::1.sync.aligned;")
#define TCG_COMMIT(mb)    asm volatile("tcgen05.commit.cta_group::1.mbarrier::arrive::one.shared::cluster.b64 [%0];" :: "r"(mb) : "memory")
#define TCG_WAIT_LD()     asm volatile("tcgen05.wait::ld.sync.aligned;" ::: "memory")
#define TCG_FENCE_BEFORE() asm volatile("tcgen05.fence::before_thread_sync;" ::: "memory")
#define TCG_FENCE_AFTER()  asm volatile("tcgen05.fence::after_thread_sync;" ::: "memory")
#define FENCE_ASYNC_SHARED() asm volatile("fence.proxy.async.shared::cta;" ::: "memory")
#define MBAR_INIT(mb, c)  asm volatile("mbarrier.init.shared.b64 [%0], %1;" :: "r"(mb), "r"((uint32_t)(c)) : "memory")
#define MBAR_INVAL(mb)    asm volatile("mbarrier.inval.shared.b64 [%0];" :: "r"(mb) : "memory")

__device__ __forceinline__ void mbar_wait(uint32_t mb, uint32_t parity) {
    asm volatile(
        "{\n\t.reg .pred P1;\n\t"
        "WAIT_LOOP_%=:\n\t"
        "mbarrier.try_wait.parity.acquire.cta.shared::cta.b64 P1, [%0], %1, 0x989680;\n\t"
        "@P1 bra.uni WAIT_DONE_%=;\n\t"
        "bra.uni WAIT_LOOP_%=;\n\t"
        "WAIT_DONE_%=:\n\t}"
        :: "r"(mb), "r"(parity) : "memory");
}

__device__ __forceinline__ void mma_ss(uint32_t d, uint64_t ad, uint64_t bd,
                                       uint32_t idesc, uint32_t en) {
    asm volatile(
        "{\n\t.reg .pred p;\n\tsetp.ne.u32 p, %4, 0;\n\t"
        "tcgen05.mma.cta_group::1.kind::f16 [%0], %1, %2, %3, {%5,%5,%5,%5}, p;\n\t}"
        :: "r"(d), "l"(ad), "l"(bd), "r"(idesc), "r"(en), "r"(0u) : "memory");
}

#define LDTM_X16(r, a) \
    asm volatile("tcgen05.ld.sync.aligned.32x32b.x16.b32 " \
        "{%0,%1,%2,%3,%4,%5,%6,%7,%8,%9,%10,%11,%12,%13,%14,%15}, [%16];" \
        : "=r"((r)[0]),"=r"((r)[1]),"=r"((r)[2]),"=r"((r)[3]), \
          "=r"((r)[4]),"=r"((r)[5]),"=r"((r)[6]),"=r"((r)[7]), \
          "=r"((r)[8]),"=r"((r)[9]),"=r"((r)[10]),"=r"((r)[11]), \
          "=r"((r)[12]),"=r"((r)[13]),"=r"((r)[14]),"=r"((r)[15]) : "r"(a))

#define LDTM_X32(r, a) \
    asm volatile("tcgen05.ld.sync.aligned.32x32b.x32.b32 " \
        "{%0,%1,%2,%3,%4,%5,%6,%7,%8,%9,%10,%11,%12,%13,%14,%15," \
        "%16,%17,%18,%19,%20,%21,%22,%23,%24,%25,%26,%27,%28,%29,%30,%31}, [%32];" \
        : "=r"((r)[0]),"=r"((r)[1]),"=r"((r)[2]),"=r"((r)[3]), \
          "=r"((r)[4]),"=r"((r)[5]),"=r"((r)[6]),"=r"((r)[7]), \
          "=r"((r)[8]),"=r"((r)[9]),"=r"((r)[10]),"=r"((r)[11]), \
          "=r"((r)[12]),"=r"((r)[13]),"=r"((r)[14]),"=r"((r)[15]), \
          "=r"((r)[16]),"=r"((r)[17]),"=r"((r)[18]),"=r"((r)[19]), \
          "=r"((r)[20]),"=r"((r)[21]),"=r"((r)[22]),"=r"((r)[23]), \
          "=r"((r)[24]),"=r"((r)[25]),"=r"((r)[26]),"=r"((r)[27]), \
          "=r"((r)[28]),"=r"((r)[29]),"=r"((r)[30]),"=r"((r)[31]) : "r"(a))

__device__ __forceinline__ uint64_t mk_desc(uint32_t addr) {
    return ((uint64_t)2 << 61) | ((uint64_t)1 << 46) | ((uint64_t)64 << 32) |
           ((uint64_t)1 << 16) | (uint64_t)((addr >> 4) & 0x3FFF);
}
#endif // HAS_TCGEN05

#define SWZ(o) ((o) ^ (((o) >> 3) & 0x70))

// Truncation split: hi = top-16-bits of fp32, lo = rn_bf16(x - hi)
__device__ __forceinline__ void split2(float x0, float x1, uint32_t& hi, uint32_t& lo) {
    uint32_t b0 = __float_as_uint(x0), b1 = __float_as_uint(x1);
    hi = __byte_perm(b0, b1, 0x7632);
    float l0 = x0 - __uint_as_float(b0 & 0xFFFF0000u);
    float l1 = x1 - __uint_as_float(b1 & 0xFFFF0000u);
    asm("cvt.rn.bf16x2.f32 %0, %1, %2;" : "=r"(lo) : "f"(l1), "f"(l0));
}

// pack two fp32 into bf16x2 word (lo half = x0)
__device__ __forceinline__ uint32_t pack_bf16x2(float x0, float x1) {
    uint32_t w;
    asm("cvt.rn.bf16x2.f32 %0, %1, %2;" : "=r"(w) : "f"(x1), "f"(x0));
    return w;
}

// 256-bit evict_last global load: 4 x u64 (= 16 bf16)
__device__ __forceinline__ void ldg_evl4x64(const void* p, uint64_t* v) {
    asm volatile("ld.global.nc.L2::evict_last.v4.b64 {%0,%1,%2,%3}, [%4];"
        : "=l"(v[0]), "=l"(v[1]), "=l"(v[2]), "=l"(v[3]) : "l"(p));
}
// 256-bit evict_last global store: 4 x u64
__device__ __forceinline__ void stg_evl4x64(void* p, const uint64_t* v) {
    asm volatile("st.global.L2::evict_last.v4.b64 [%0], {%1,%2,%3,%4};"
        :: "l"(p), "l"(v[0]), "l"(v[1]), "l"(v[2]), "l"(v[3]) : "memory");
}

// ---------------------------------------------------------------------------
// MLP kernel — R3/R7 structure: 128 rows/CTA, grid 1024, bf16 epilogue.
// ---------------------------------------------------------------------------
__global__ __launch_bounds__(256, 2)
void mlp_kernel(const float* __restrict__ X,
                const float* __restrict__ W1,
                const float* __restrict__ b1,
                const float* __restrict__ W2,
                const float* __restrict__ b2)
{
    extern __shared__ char smem[];
#if HAS_TCGEN05
#define SM_AHI 1024
#define SM_ALO 17408
#define SM_BHI 33792
#define SM_BLO 50176
#define SM_B1  66560
#define SM_B2  67072
    const uint32_t sb  = smem_u32(smem);
    const int tid = threadIdx.x, wid = tid >> 5, lid = tid & 31;
    const long rowBase = (long)blockIdx.x * 128;

    float* b1s = (float*)(smem + SM_B1);
    float* b2s = (float*)(smem + SM_B2);

    if (wid == 0) { TCG_ALLOC(sb + 0, 256); TCG_RELINQ(); }
    if (tid == 0) MBAR_INIT(sb + 8, 1);
    if (tid < 128) { b1s[tid] = b1[tid]; b2s[tid] = b2[tid]; }
    __syncthreads();

    uint32_t tmem;
    asm volatile("ld.shared.b32 %0, [%1];" : "=r"(tmem) : "r"(sb + 0));

    const uint32_t idesc = (1u << 4) | (1u << 7) | (1u << 10) |
                           ((DOUT / 8) << 17) | ((128 / 16) << 24);
    const uint64_t adhi = mk_desc(sb + SM_AHI);
    const uint64_t adlo = mk_desc(sb + SM_ALO);
    const uint64_t bdhi = mk_desc(sb + SM_BHI);
    const uint64_t bdlo = mk_desc(sb + SM_BLO);

    uint32_t parity = 0;

    // ================= GEMM1: 4 K-chunks of 64 =================
    for (int kb = 0; kb < 4; kb++) {
        const float* Xc = X + rowBase * DIN + kb * 64;
#pragma unroll
        for (int it = 0; it < 4; it++) {
            int f  = it * 256 + tid;
            int r  = f >> 3;
            int c8 = f & 7;
            const float4* src = (const float4*)(Xc + (size_t)r * DIN + c8 * 8);
            float4 va = src[0], vb = src[1];
            uint32_t h0, l0, h1, l1, h2, l2, h3, l3;
            split2(va.x, va.y, h0, l0);
            split2(va.z, va.w, h1, l1);
            split2(vb.x, vb.y, h2, l2);
            split2(vb.z, vb.w, h3, l3);
            uint32_t off = SWZ((uint32_t)(r * 128 + c8 * 16));
            *(uint4*)(smem + SM_AHI + off) = make_uint4(h0, h1, h2, h3);
            *(uint4*)(smem + SM_ALO + off) = make_uint4(l0, l1, l2, l3);
        }
#pragma unroll
        for (int it = 0; it < 8; it++) {
            int f = it * 256 + tid;
            int g = f & 1023;
            int n = g >> 3, c16 = g & 7;
            const __nv_bfloat16* wsrc = (f < 1024) ? g_w1t_hi : g_w1t_lo;
            uint4 v = *(const uint4*)(wsrc + (size_t)n * DIN + kb * 64 + c16 * 8);
            uint32_t dst = ((f < 1024) ? SM_BHI : SM_BLO) + SWZ((uint32_t)(n * 128 + c16 * 16));
            *(uint4*)(smem + dst) = v;
        }
        __syncthreads();

        if (wid == 0) {
            FENCE_ASYNC_SHARED();
            if (elect_one()) {
#pragma unroll
                for (int ks = 0; ks < 4; ks++)
                    mma_ss(tmem, adhi + ks * 2, bdhi + ks * 2, idesc, (kb > 0) || (ks > 0));
#pragma unroll
                for (int ks = 0; ks < 4; ks++)
                    mma_ss(tmem, adhi + ks * 2, bdlo + ks * 2, idesc, 1);
#pragma unroll
                for (int ks = 0; ks < 4; ks++)
                    mma_ss(tmem, adlo + ks * 2, bdhi + ks * 2, idesc, 1);
                TCG_COMMIT(sb + 8);
            }
        }
        mbar_wait(sb + 8, parity); parity ^= 1;
        TCG_FENCE_AFTER();
        __syncthreads();
    }

    // ================= GEMM2: 2 K-chunks of 64 =================
    for (int c2 = 0; c2 < 2; c2++) {
        if (wid < 4) {
            int row = wid * 32 + lid;
#pragma unroll
            for (int part = 0; part < 4; part++) {
                uint32_t r16[16];
                LDTM_X16(r16, tmem + c2 * 64 + part * 16);
                TCG_WAIT_LD();
#pragma unroll
                for (int grp = 0; grp < 2; grp++) {
                    uint32_t hs[4], ls[4];
#pragma unroll
                    for (int q = 0; q < 4; q++) {
                        int c = grp * 8 + q * 2;
                        float x0 = __uint_as_float(r16[c])     + b1s[c2 * 64 + part * 16 + c];
                        float x1 = __uint_as_float(r16[c + 1]) + b1s[c2 * 64 + part * 16 + c + 1];
                        x0 = fmaxf(x0, 0.f);
                        x1 = fmaxf(x1, 0.f);
                        split2(x0, x1, hs[q], ls[q]);
                    }
                    uint32_t off = SWZ((uint32_t)(row * 128 + (part * 16 + grp * 8) * 2));
                    *(uint4*)(smem + SM_AHI + off) = make_uint4(hs[0], hs[1], hs[2], hs[3]);
                    *(uint4*)(smem + SM_ALO + off) = make_uint4(ls[0], ls[1], ls[2], ls[3]);
                }
            }
        } else {
            int t2 = tid - 128;
#pragma unroll
            for (int it = 0; it < 16; it++) {
                int f = it * 128 + t2;
                int g = f & 1023;
                int n = g >> 3, c16 = g & 7;
                const __nv_bfloat16* wsrc = (f < 1024) ? g_w2t_hi : g_w2t_lo;
                uint4 v = *(const uint4*)(wsrc + (size_t)n * DOUT + c2 * 64 + c16 * 8);
                uint32_t dst = ((f < 1024) ? SM_BHI : SM_BLO) + SWZ((uint32_t)(n * 128 + c16 * 16));
                *(uint4*)(smem + dst) = v;
            }
        }
        __syncthreads();

        if (wid == 0) {
            FENCE_ASYNC_SHARED();
            if (elect_one()) {
#pragma unroll
                for (int ks = 0; ks < 4; ks++)
                    mma_ss(tmem + 128, adhi + ks * 2, bdhi + ks * 2, idesc, (c2 > 0) || (ks > 0));
#pragma unroll
                for (int ks = 0; ks < 4; ks++)
                    mma_ss(tmem + 128, adhi + ks * 2, bdlo + ks * 2, idesc, 1);
#pragma unroll
                for (int ks = 0; ks < 4; ks++)
                    mma_ss(tmem + 128, adlo + ks * 2, bdhi + ks * 2, idesc, 1);
                TCG_COMMIT(sb + 8);
            }
        }
        mbar_wait(sb + 8, parity); parity ^= 1;
        TCG_FENCE_AFTER();
        __syncthreads();
    }

    // ================= Epilogue: bf16(D2 + b2) -> g_h =================
    if (wid < 4) {
        int row = wid * 32 + lid;
        __nv_bfloat16* dst = g_h + (size_t)(rowBase + row) * DOUT;
#pragma unroll
        for (int grp = 0; grp < 4; grp++) {
            uint32_t r32[32];
            LDTM_X32(r32, tmem + 128 + grp * 32);
            TCG_WAIT_LD();
            uint64_t w64[8];
#pragma unroll
            for (int q = 0; q < 8; q++) {
                float x0 = __uint_as_float(r32[q * 4 + 0]) + b2s[grp * 32 + q * 4 + 0];
                float x1 = __uint_as_float(r32[q * 4 + 1]) + b2s[grp * 32 + q * 4 + 1];
                float x2 = __uint_as_float(r32[q * 4 + 2]) + b2s[grp * 32 + q * 4 + 2];
                float x3 = __uint_as_float(r32[q * 4 + 3]) + b2s[grp * 32 + q * 4 + 3];
                uint32_t wlo = pack_bf16x2(x0, x1);
                uint32_t whi = pack_bf16x2(x2, x3);
                w64[q] = (uint64_t)wlo | ((uint64_t)whi << 32);
            }
            stg_evl4x64(dst + grp * 32,      w64);
            stg_evl4x64(dst + grp * 32 + 16, w64 + 4);
        }
        TCG_FENCE_BEFORE();
    }
    __syncthreads();
    if (tid == 0) MBAR_INVAL(sb + 8);
    __syncthreads();
    if (wid == 0) TCG_DEALLOC(tmem, 256);

#else  // ===================== fp32 FFMA fallback =====================
    float (*xs)[68]   = (float (*)[68])(smem);
    float (*ws)[128]  = (float (*)[128])(smem + 32 * 68 * 4);
    float (*h1T)[68]  = (float (*)[68])(smem + 32 * 68 * 4 + 32 * 128 * 4);

    const int tid = threadIdx.x;
    const int tr  = tid >> 5;
    const int tc  = tid & 31;

    for (int half = 0; half < 2; half++) {
        const long rowBase = (long)blockIdx.x * 128 + half * 64;
        float acc[8][4];
#pragma unroll
        for (int r = 0; r < 8; r++)
#pragma unroll
            for (int c = 0; c < 4; c++) acc[r][c] = 0.f;

        for (int kb = 0; kb < DIN; kb += 32) {
#pragma unroll
            for (int it = 0; it < 2; it++) {
                int f = tid + it * 256;
                int r  = f >> 3;
                int k4 = f & 7;
                float4 v = *(const float4*)(X + (rowBase + r) * DIN + kb + k4 * 4);
                xs[k4 * 4 + 0][r] = v.x;
                xs[k4 * 4 + 1][r] = v.y;
                xs[k4 * 4 + 2][r] = v.z;
                xs[k4 * 4 + 3][r] = v.w;
            }
#pragma unroll
            for (int it = 0; it < 4; it++) {
                int f  = tid + it * 256;
                int kr = f >> 5;
                int c4 = f & 31;
                *(float4*)&ws[kr][c4 * 4] =
                    *(const float4*)(W1 + (size_t)(kb + kr) * DOUT + c4 * 4);
            }
            __syncthreads();
#pragma unroll
            for (int kk = 0; kk < 32; kk++) {
                float4 xa = *(float4*)&xs[kk][tr * 8];
                float4 xb = *(float4*)&xs[kk][tr * 8 + 4];
                float4 w  = *(float4*)&ws[kk][tc * 4];
                float xr[8] = {xa.x, xa.y, xa.z, xa.w, xb.x, xb.y, xb.z, xb.w};
                float wr[4] = {w.x, w.y, w.z, w.w};
#pragma unroll
                for (int r = 0; r < 8; r++)
#pragma unroll
                    for (int c = 0; c < 4; c++)
                        acc[r][c] = fmaf(xr[r], wr[c], acc[r][c]);
            }
            __syncthreads();
        }
        {
            float bb[4];
#pragma unroll
            for (int c = 0; c < 4; c++) bb[c] = b1[tc * 4 + c];
#pragma unroll
            for (int r = 0; r < 8; r++)
#pragma unroll
                for (int c = 0; c < 4; c++) {
                    float v = acc[r][c] + bb[c];
                    h1T[tc * 4 + c][tr * 8 + r] = fmaxf(v, 0.f);
                    acc[r][c] = 0.f;
                }
        }
        __syncthreads();

        for (int kb = 0; kb < DOUT; kb += 32) {
#pragma unroll
            for (int it = 0; it < 4; it++) {
                int f  = tid + it * 256;
                int kr = f >> 5;
                int c4 = f & 31;
                *(float4*)&ws[kr][c4 * 4] =
                    *(const float4*)(W2 + (size_t)(kb + kr) * DOUT + c4 * 4);
            }
            __syncthreads();
#pragma unroll
            for (int kk = 0; kk < 32; kk++) {
                float4 xa = *(float4*)&h1T[kb + kk][tr * 8];
                float4 xb = *(float4*)&h1T[kb + kk][tr * 8 + 4];
                float4 w  = *(float4*)&ws[kk][tc * 4];
                float xr[8] = {xa.x, xa.y, xa.z, xa.w, xb.x, xb.y, xb.z, xb.w};
                float wr[4] = {w.x, w.y, w.z, w.w};
#pragma unroll
                for (int r = 0; r < 8; r++)
#pragma unroll
                    for (int c = 0; c < 4; c++)
                        acc[r][c] = fmaf(xr[r], wr[c], acc[r][c]);
            }
            __syncthreads();
        }
        {
            float bb[4];
#pragma unroll
            for (int c = 0; c < 4; c++) bb[c] = b2[tc * 4 + c];
#pragma unroll
            for (int r = 0; r < 8; r++) {
                float x0 = acc[r][0] + bb[0];
                float x1 = acc[r][1] + bb[1];
                float x2 = acc[r][2] + bb[2];
                float x3 = acc[r][3] + bb[3];
                uint2 o;
                o.x = pack_bf16x2(x0, x1);
                o.y = pack_bf16x2(x2, x3);
                *(uint2*)(g_h + (rowBase + tr * 8 + r) * DOUT + tc * 4) = o;
            }
        }
        __syncthreads();
    }
#endif
}

// ---------------------------------------------------------------------------
// Gather kernel, n-sliced schedule: blockIdx.x = n * 2048 + u_block.
// For a fixed n, gather touches only the 4 MB slice g_h[:, n, :] -> L2 resident.
// 8 lanes per (u,n) row, 16 bf16 (32B) per lane; 32 rows per block.
// ---------------------------------------------------------------------------
__global__ __launch_bounds__(256)
void gather_add_kernel(const float* __restrict__ up,
                       const int*   __restrict__ idx,
                       float*       __restrict__ out)
{
    const int n      = blockIdx.x >> 11;            // 0..7 (n-major over passes)
    const int ublock = blockIdx.x & 2047;           // 0..2047
    const int lane   = threadIdx.x & 7;             // 16-bf16 chunk id
    const long u     = (long)ublock * 32 + (threadIdx.x >> 3);
    const long row   = u * NNm + n;                 // output row (u,n)

    const int* ip = idx + row * 3;
    int i0 = __ldg(ip + 0);
    int i1 = __ldg(ip + 1);
    int i2 = __ldg(ip + 2);

    const __nv_bfloat16* p0 = g_h + (size_t)(i0 * NNm + n) * DOUT + lane * 16;
    const __nv_bfloat16* p1 = g_h + (size_t)(i1 * NNm + n) * DOUT + lane * 16;
    const __nv_bfloat16* p2 = g_h + (size_t)(i2 * NNm + n) * DOUT + lane * 16;

    uint64_t ga[4], gb[4], gc[4];
    ldg_evl4x64(p0, ga);
    ldg_evl4x64(p1, gb);
    ldg_evl4x64(p2, gc);

    const float4* upp = (const float4*)(up + row * DOUT + lane * 16);
    float4 u4[4];
    u4[0] = __ldcs(upp + 0);
    u4[1] = __ldcs(upp + 1);
    u4[2] = __ldcs(upp + 2);
    u4[3] = __ldcs(upp + 3);

    const float inv3 = 1.0f / 3.0f;
    float4 o[4];
    float* uo = (float*)u4;
    float* oo = (float*)o;
#pragma unroll
    for (int q = 0; q < 4; q++) {
#pragma unroll
        for (int hw = 0; hw < 2; hw++) {
            uint32_t wa = (uint32_t)(ga[q] >> (hw * 32));
            uint32_t wb = (uint32_t)(gb[q] >> (hw * 32));
            uint32_t wc = (uint32_t)(gc[q] >> (hw * 32));
            float a0 = __uint_as_float(wa << 16), a1 = __uint_as_float(wa & 0xFFFF0000u);
            float b0 = __uint_as_float(wb << 16), b1 = __uint_as_float(wb & 0xFFFF0000u);
            float c0 = __uint_as_float(wc << 16), c1 = __uint_as_float(wc & 0xFFFF0000u);
            int e = q * 4 + hw * 2;
            oo[e + 0] = fmaf(a0 + b0 + c0, inv3, uo[e + 0]);
            oo[e + 1] = fmaf(a1 + b1 + c1, inv3, uo[e + 1]);
        }
    }

    float4* op = (float4*)(out + row * DOUT + lane * 16);
    __stcs(op + 0, o[0]);
    __stcs(op + 1, o[1]);
    __stcs(op + 2, o[2]);
    __stcs(op + 3, o[3]);
}

// ---------------------------------------------------------------------------
// Launch: inputs = down_features, up_features, idx, W1, b1, W2, b2
// ---------------------------------------------------------------------------
extern "C" void kernel_launch(void* const* d_in, const int* in_sizes, int n_in,
                              void* d_out, int out_size)
{
    const float* down = (const float*)d_in[0];
    const float* up   = (const float*)d_in[1];
    const int*   idx  = (const int*)  d_in[2];
    const float* W1   = (const float*)d_in[3];
    const float* b1   = (const float*)d_in[4];
    const float* W2   = (const float*)d_in[5];
    const float* b2   = (const float*)d_in[6];
    float* out = (float*)d_out;

    static int smem_set = 0;
    if (!smem_set) {
        cudaFuncSetAttribute(mlp_kernel,
                             cudaFuncAttributeMaxDynamicSharedMemorySize, SMEM_TOTAL);
        smem_set = 1;
    }

    // 1. Split weights into bf16 hi/lo
    wsplit_kernel<<<192, 256>>>(W1, W2);

    // 2. MLP -> g_h bf16 (128 rows per CTA, grid 1024)
    mlp_kernel<<<M_ROWS / 128, 256, SMEM_TOTAL>>>(down, W1, b1, W2, b2);

    // 3. Gather + mean + add, n-sliced (8 passes x 2048 blocks)
    gather_add_kernel<<<8 * 2048, 256>>>(up, idx, out);
}

// round 11
// speedup vs baseline: 1.2028x; 1.0045x over previous
#include <cuda_runtime.h>
#include <cuda_bf16.h>
#include <cstdint>

// Problem constants
#define LDm   16384
#define LUm   65536
#define NNm   8
#define DIN   256
#define DOUT  128
#define M_ROWS (LDm * NNm)            // 131072 MLP rows
#define OUT_ROWS ((long)LUm * NNm)    // 524288 output rows

// Arch-specific (sm_103a/sm_100a) pass?
#if defined(__CUDA_ARCH__) && (defined(__CUDA_ARCH_FEAT_SM103_ALL) || \
    defined(__CUDA_ARCH_FEAT_SM100_ALL) || \
    (defined(__CUDA_ARCH_SPECIFIC__) && (__CUDA_ARCH_SPECIFIC__ >= 1000)))
#define HAS_TCGEN05 1
#else
#define HAS_TCGEN05 0
#endif

// Scratch: h = relu(x@W1+b1)@W2+b2  [LD, N, D_OUT] in bf16 (32 MB)
__device__ __align__(128) __nv_bfloat16 g_h[(size_t)M_ROWS * DOUT];
// Precomputed bf16 hi/lo splits of W1^T, W2^T (B operands, N x K, K-major)
__device__ __align__(16) __nv_bfloat16 g_w1t_hi[DOUT * DIN];
__device__ __align__(16) __nv_bfloat16 g_w1t_lo[DOUT * DIN];
__device__ __align__(16) __nv_bfloat16 g_w2t_hi[DOUT * DOUT];
__device__ __align__(16) __nv_bfloat16 g_w2t_lo[DOUT * DOUT];

#define SMEM_TOTAL 67584

// ---------------------------------------------------------------------------
// Pre-kernel: split W1^T / W2^T into bf16 hi/lo.
// Index mapping is k-major so the W reads are COALESCED (writes scatter at
// 512B stride into a 96 KB L2-resident footprint — write-merged, no stall).
// ---------------------------------------------------------------------------
__global__ void wsplit_kernel(const float* __restrict__ W1,
                              const float* __restrict__ W2)
{
    int t = blockIdx.x * blockDim.x + threadIdx.x;
    if (t < DIN * DOUT) {                   // W1: t = k*128 + n (coalesced read)
        int k = t >> 7, n = t & 127;
        float x = W1[t];
        uint32_t b = __float_as_uint(x);
        float hf = __uint_as_float(b & 0xFFFF0000u);
        g_w1t_hi[n * DIN + k] = __ushort_as_bfloat16((unsigned short)(b >> 16));
        g_w1t_lo[n * DIN + k] = __float2bfloat16(x - hf);
    } else {
        int t2 = t - DIN * DOUT;
        if (t2 < DOUT * DOUT) {             // W2: t2 = k*128 + n
            int k = t2 >> 7, n = t2 & 127;
            float x = W2[t2];
            uint32_t b = __float_as_uint(x);
            float hf = __uint_as_float(b & 0xFFFF0000u);
            g_w2t_hi[n * DOUT + k] = __ushort_as_bfloat16((unsigned short)(b >> 16));
            g_w2t_lo[n * DOUT + k] = __float2bfloat16(x - hf);
        }
    }
}

#if HAS_TCGEN05
// ---------------------------------------------------------------------------
// PTX helpers
// ---------------------------------------------------------------------------
__device__ __forceinline__ uint32_t smem_u32(const void* p) {
    uint32_t a;
    asm("{ .reg .u64 t; cvta.to.shared.u64 t, %1; cvt.u32.u64 %0, t; }"
        : "=r"(a) : "l"(p));
    return a;
}
__device__ __forceinline__ uint32_t elect_one() {
    uint32_t p;
    asm volatile("{ .reg .pred p; elect.sync _|p, 0xFFFFFFFF; selp.b32 %0,1,0,p; }"
                 : "=r"(p));
    return p;
}
#define TCG_ALLOC(sm, n)  asm volatile("tcgen05.alloc.cta_group::1.sync.aligned.shared::cta.b32 [%0], %1;" :: "r"(sm), "r"((uint32_t)(n)) : "memory")
#define TCG_DEALLOC(t, n) asm volatile("tcgen05.dealloc.cta_group::1.sync.aligned.b32 %0, %1;" :: "r"(t), "r"((uint32_t)(n)))
#define TCG_RELINQ()      asm volatile("tcgen05.relinquish_alloc_permit.cta_group::1.sync.aligned;")
#define TCG_COMMIT(mb)    asm volatile("tcgen05.commit.cta_group::1.mbarrier::arrive::one.shared::cluster.b64 [%0];" :: "r"(mb) : "memory")
#define TCG_WAIT_LD()     asm volatile("tcgen05.wait::ld.sync.aligned;" ::: "memory")
#define TCG_FENCE_BEFORE() asm volatile("tcgen05.fence::before_thread_sync;" ::: "memory")
#define TCG_FENCE_AFTER()  asm volatile("tcgen05.fence::after_thread_sync;" ::: "memory")
#define FENCE_ASYNC_SHARED() asm volatile("fence.proxy.async.shared::cta;" ::: "memory")
#define MBAR_INIT(mb, c)  asm volatile("mbarrier.init.shared.b64 [%0], %1;" :: "r"(mb), "r"((uint32_t)(c)) : "memory")
#define MBAR_INVAL(mb)    asm volatile("mbarrier.inval.shared.b64 [%0];" :: "r"(mb) : "memory")

__device__ __forceinline__ void mbar_wait(uint32_t mb, uint32_t parity) {
    asm volatile(
        "{\n\t.reg .pred P1;\n\t"
        "WAIT_LOOP_%=:\n\t"
        "mbarrier.try_wait.parity.acquire.cta.shared::cta.b64 P1, [%0], %1, 0x989680;\n\t"
        "@P1 bra.uni WAIT_DONE_%=;\n\t"
        "bra.uni WAIT_LOOP_%=;\n\t"
        "WAIT_DONE_%=:\n\t}"
        :: "r"(mb), "r"(parity) : "memory");
}

__device__ __forceinline__ void mma_ss(uint32_t d, uint64_t ad, uint64_t bd,
                                       uint32_t idesc, uint32_t en) {
    asm volatile(
        "{\n\t.reg .pred p;\n\tsetp.ne.u32 p, %4, 0;\n\t"
        "tcgen05.mma.cta_group::1.kind::f16 [%0], %1, %2, %3, {%5,%5,%5,%5}, p;\n\t}"
        :: "r"(d), "l"(ad), "l"(bd), "r"(idesc), "r"(en), "r"(0u) : "memory");
}

#define LDTM_X16(r, a) \
    asm volatile("tcgen05.ld.sync.aligned.32x32b.x16.b32 " \
        "{%0,%1,%2,%3,%4,%5,%6,%7,%8,%9,%10,%11,%12,%13,%14,%15}, [%16];" \
        : "=r"((r)[0]),"=r"((r)[1]),"=r"((r)[2]),"=r"((r)[3]), \
          "=r"((r)[4]),"=r"((r)[5]),"=r"((r)[6]),"=r"((r)[7]), \
          "=r"((r)[8]),"=r"((r)[9]),"=r"((r)[10]),"=r"((r)[11]), \
          "=r"((r)[12]),"=r"((r)[13]),"=r"((r)[14]),"=r"((r)[15]) : "r"(a))

#define LDTM_X32(r, a) \
    asm volatile("tcgen05.ld.sync.aligned.32x32b.x32.b32 " \
        "{%0,%1,%2,%3,%4,%5,%6,%7,%8,%9,%10,%11,%12,%13,%14,%15," \
        "%16,%17,%18,%19,%20,%21,%22,%23,%24,%25,%26,%27,%28,%29,%30,%31}, [%32];" \
        : "=r"((r)[0]),"=r"((r)[1]),"=r"((r)[2]),"=r"((r)[3]), \
          "=r"((r)[4]),"=r"((r)[5]),"=r"((r)[6]),"=r"((r)[7]), \
          "=r"((r)[8]),"=r"((r)[9]),"=r"((r)[10]),"=r"((r)[11]), \
          "=r"((r)[12]),"=r"((r)[13]),"=r"((r)[14]),"=r"((r)[15]), \
          "=r"((r)[16]),"=r"((r)[17]),"=r"((r)[18]),"=r"((r)[19]), \
          "=r"((r)[20]),"=r"((r)[21]),"=r"((r)[22]),"=r"((r)[23]), \
          "=r"((r)[24]),"=r"((r)[25]),"=r"((r)[26]),"=r"((r)[27]), \
          "=r"((r)[28]),"=r"((r)[29]),"=r"((r)[30]),"=r"((r)[31]) : "r"(a))

__device__ __forceinline__ uint64_t mk_desc(uint32_t addr) {
    return ((uint64_t)2 << 61) | ((uint64_t)1 << 46) | ((uint64_t)64 << 32) |
           ((uint64_t)1 << 16) | (uint64_t)((addr >> 4) & 0x3FFF);
}
#endif // HAS_TCGEN05

#define SWZ(o) ((o) ^ (((o) >> 3) & 0x70))

// Truncation split: hi = top-16-bits of fp32, lo = rn_bf16(x - hi)
__device__ __forceinline__ void split2(float x0, float x1, uint32_t& hi, uint32_t& lo) {
    uint32_t b0 = __float_as_uint(x0), b1 = __float_as_uint(x1);
    hi = __byte_perm(b0, b1, 0x7632);
    float l0 = x0 - __uint_as_float(b0 & 0xFFFF0000u);
    float l1 = x1 - __uint_as_float(b1 & 0xFFFF0000u);
    asm("cvt.rn.bf16x2.f32 %0, %1, %2;" : "=r"(lo) : "f"(l1), "f"(l0));
}

// pack two fp32 into bf16x2 word (lo half = x0)
__device__ __forceinline__ uint32_t pack_bf16x2(float x0, float x1) {
    uint32_t w;
    asm("cvt.rn.bf16x2.f32 %0, %1, %2;" : "=r"(w) : "f"(x1), "f"(x0));
    return w;
}

// 256-bit evict_last global load: 4 x u64 (= 16 bf16)
__device__ __forceinline__ void ldg_evl4x64(const void* p, uint64_t* v) {
    asm volatile("ld.global.nc.L2::evict_last.v4.b64 {%0,%1,%2,%3}, [%4];"
        : "=l"(v[0]), "=l"(v[1]), "=l"(v[2]), "=l"(v[3]) : "l"(p));
}
// 256-bit evict_last global store: 4 x u64
__device__ __forceinline__ void stg_evl4x64(void* p, const uint64_t* v) {
    asm volatile("st.global.L2::evict_last.v4.b64 [%0], {%1,%2,%3,%4};"
        :: "l"(p), "l"(v[0]), "l"(v[1]), "l"(v[2]), "l"(v[3]) : "memory");
}

// ---------------------------------------------------------------------------
// MLP kernel — 128 rows/CTA, grid 1024, bf16 epilogue.
// Trailing __syncthreads after mbar_wait removed (mbar+fence order smem reuse;
// per-tid smem slot ownership is identical across rounds).
// ---------------------------------------------------------------------------
__global__ __launch_bounds__(256, 2)
void mlp_kernel(const float* __restrict__ X,
                const float* __restrict__ W1,
                const float* __restrict__ b1,
                const float* __restrict__ W2,
                const float* __restrict__ b2)
{
    extern __shared__ char smem[];
#if HAS_TCGEN05
#define SM_AHI 1024
#define SM_ALO 17408
#define SM_BHI 33792
#define SM_BLO 50176
#define SM_B1  66560
#define SM_B2  67072
    const uint32_t sb  = smem_u32(smem);
    const int tid = threadIdx.x, wid = tid >> 5, lid = tid & 31;
    const long rowBase = (long)blockIdx.x * 128;

    float* b1s = (float*)(smem + SM_B1);
    float* b2s = (float*)(smem + SM_B2);

    if (wid == 0) { TCG_ALLOC(sb + 0, 256); TCG_RELINQ(); }
    if (tid == 0) MBAR_INIT(sb + 8, 1);
    if (tid < 128) { b1s[tid] = b1[tid]; b2s[tid] = b2[tid]; }
    __syncthreads();

    uint32_t tmem;
    asm volatile("ld.shared.b32 %0, [%1];" : "=r"(tmem) : "r"(sb + 0));

    const uint32_t idesc = (1u << 4) | (1u << 7) | (1u << 10) |
                           ((DOUT / 8) << 17) | ((128 / 16) << 24);
    const uint64_t adhi = mk_desc(sb + SM_AHI);
    const uint64_t adlo = mk_desc(sb + SM_ALO);
    const uint64_t bdhi = mk_desc(sb + SM_BHI);
    const uint64_t bdlo = mk_desc(sb + SM_BLO);

    uint32_t parity = 0;

    // ================= GEMM1: 4 K-chunks of 64 =================
    for (int kb = 0; kb < 4; kb++) {
        const float* Xc = X + rowBase * DIN + kb * 64;
#pragma unroll
        for (int it = 0; it < 4; it++) {
            int f  = it * 256 + tid;
            int r  = f >> 3;
            int c8 = f & 7;
            const float4* src = (const float4*)(Xc + (size_t)r * DIN + c8 * 8);
            float4 va = src[0], vb = src[1];
            uint32_t h0, l0, h1, l1, h2, l2, h3, l3;
            split2(va.x, va.y, h0, l0);
            split2(va.z, va.w, h1, l1);
            split2(vb.x, vb.y, h2, l2);
            split2(vb.z, vb.w, h3, l3);
            uint32_t off = SWZ((uint32_t)(r * 128 + c8 * 16));
            *(uint4*)(smem + SM_AHI + off) = make_uint4(h0, h1, h2, h3);
            *(uint4*)(smem + SM_ALO + off) = make_uint4(l0, l1, l2, l3);
        }
#pragma unroll
        for (int it = 0; it < 8; it++) {
            int f = it * 256 + tid;
            int g = f & 1023;
            int n = g >> 3, c16 = g & 7;
            const __nv_bfloat16* wsrc = (f < 1024) ? g_w1t_hi : g_w1t_lo;
            uint4 v = *(const uint4*)(wsrc + (size_t)n * DIN + kb * 64 + c16 * 8);
            uint32_t dst = ((f < 1024) ? SM_BHI : SM_BLO) + SWZ((uint32_t)(n * 128 + c16 * 16));
            *(uint4*)(smem + dst) = v;
        }
        __syncthreads();

        if (wid == 0) {
            FENCE_ASYNC_SHARED();
            if (elect_one()) {
#pragma unroll
                for (int ks = 0; ks < 4; ks++)
                    mma_ss(tmem, adhi + ks * 2, bdhi + ks * 2, idesc, (kb > 0) || (ks > 0));
#pragma unroll
                for (int ks = 0; ks < 4; ks++)
                    mma_ss(tmem, adhi + ks * 2, bdlo + ks * 2, idesc, 1);
#pragma unroll
                for (int ks = 0; ks < 4; ks++)
                    mma_ss(tmem, adlo + ks * 2, bdhi + ks * 2, idesc, 1);
                TCG_COMMIT(sb + 8);
            }
        }
        mbar_wait(sb + 8, parity); parity ^= 1;
        TCG_FENCE_AFTER();
    }

    // ================= GEMM2: 2 K-chunks of 64 =================
    for (int c2 = 0; c2 < 2; c2++) {
        if (wid < 4) {
            int row = wid * 32 + lid;
#pragma unroll
            for (int part = 0; part < 4; part++) {
                uint32_t r16[16];
                LDTM_X16(r16, tmem + c2 * 64 + part * 16);
                TCG_WAIT_LD();
#pragma unroll
                for (int grp = 0; grp < 2; grp++) {
                    uint32_t hs[4], ls[4];
#pragma unroll
                    for (int q = 0; q < 4; q++) {
                        int c = grp * 8 + q * 2;
                        float x0 = __uint_as_float(r16[c])     + b1s[c2 * 64 + part * 16 + c];
                        float x1 = __uint_as_float(r16[c + 1]) + b1s[c2 * 64 + part * 16 + c + 1];
                        x0 = fmaxf(x0, 0.f);
                        x1 = fmaxf(x1, 0.f);
                        split2(x0, x1, hs[q], ls[q]);
                    }
                    uint32_t off = SWZ((uint32_t)(row * 128 + (part * 16 + grp * 8) * 2));
                    *(uint4*)(smem + SM_AHI + off) = make_uint4(hs[0], hs[1], hs[2], hs[3]);
                    *(uint4*)(smem + SM_ALO + off) = make_uint4(ls[0], ls[1], ls[2], ls[3]);
                }
            }
        } else {
            int t2 = tid - 128;
#pragma unroll
            for (int it = 0; it < 16; it++) {
                int f = it * 128 + t2;
                int g = f & 1023;
                int n = g >> 3, c16 = g & 7;
                const __nv_bfloat16* wsrc = (f < 1024) ? g_w2t_hi : g_w2t_lo;
                uint4 v = *(const uint4*)(wsrc + (size_t)n * DOUT + c2 * 64 + c16 * 8);
                uint32_t dst = ((f < 1024) ? SM_BHI : SM_BLO) + SWZ((uint32_t)(n * 128 + c16 * 16));
                *(uint4*)(smem + dst) = v;
            }
        }
        __syncthreads();

        if (wid == 0) {
            FENCE_ASYNC_SHARED();
            if (elect_one()) {
#pragma unroll
                for (int ks = 0; ks < 4; ks++)
                    mma_ss(tmem + 128, adhi + ks * 2, bdhi + ks * 2, idesc, (c2 > 0) || (ks > 0));
#pragma unroll
                for (int ks = 0; ks < 4; ks++)
                    mma_ss(tmem + 128, adhi + ks * 2, bdlo + ks * 2, idesc, 1);
#pragma unroll
                for (int ks = 0; ks < 4; ks++)
                    mma_ss(tmem + 128, adlo + ks * 2, bdhi + ks * 2, idesc, 1);
                TCG_COMMIT(sb + 8);
            }
        }
        mbar_wait(sb + 8, parity); parity ^= 1;
        TCG_FENCE_AFTER();
    }

    // ================= Epilogue: bf16(D2 + b2) -> g_h =================
    if (wid < 4) {
        int row = wid * 32 + lid;
        __nv_bfloat16* dst = g_h + (size_t)(rowBase + row) * DOUT;
#pragma unroll
        for (int grp = 0; grp < 4; grp++) {
            uint32_t r32[32];
            LDTM_X32(r32, tmem + 128 + grp * 32);
            TCG_WAIT_LD();
            uint64_t w64[8];
#pragma unroll
            for (int q = 0; q < 8; q++) {
                float x0 = __uint_as_float(r32[q * 4 + 0]) + b2s[grp * 32 + q * 4 + 0];
                float x1 = __uint_as_float(r32[q * 4 + 1]) + b2s[grp * 32 + q * 4 + 1];
                float x2 = __uint_as_float(r32[q * 4 + 2]) + b2s[grp * 32 + q * 4 + 2];
                float x3 = __uint_as_float(r32[q * 4 + 3]) + b2s[grp * 32 + q * 4 + 3];
                uint32_t wlo = pack_bf16x2(x0, x1);
                uint32_t whi = pack_bf16x2(x2, x3);
                w64[q] = (uint64_t)wlo | ((uint64_t)whi << 32);
            }
            stg_evl4x64(dst + grp * 32,      w64);
            stg_evl4x64(dst + grp * 32 + 16, w64 + 4);
        }
        TCG_FENCE_BEFORE();
    }
    __syncthreads();
    if (tid == 0) MBAR_INVAL(sb + 8);
    __syncthreads();
    if (wid == 0) TCG_DEALLOC(tmem, 256);

#else  // ===================== fp32 FFMA fallback =====================
    float (*xs)[68]   = (float (*)[68])(smem);
    float (*ws)[128]  = (float (*)[128])(smem + 32 * 68 * 4);
    float (*h1T)[68]  = (float (*)[68])(smem + 32 * 68 * 4 + 32 * 128 * 4);

    const int tid = threadIdx.x;
    const int tr  = tid >> 5;
    const int tc  = tid & 31;

    for (int half = 0; half < 2; half++) {
        const long rowBase = (long)blockIdx.x * 128 + half * 64;
        float acc[8][4];
#pragma unroll
        for (int r = 0; r < 8; r++)
#pragma unroll
            for (int c = 0; c < 4; c++) acc[r][c] = 0.f;

        for (int kb = 0; kb < DIN; kb += 32) {
#pragma unroll
            for (int it = 0; it < 2; it++) {
                int f = tid + it * 256;
                int r  = f >> 3;
                int k4 = f & 7;
                float4 v = *(const float4*)(X + (rowBase + r) * DIN + kb + k4 * 4);
                xs[k4 * 4 + 0][r] = v.x;
                xs[k4 * 4 + 1][r] = v.y;
                xs[k4 * 4 + 2][r] = v.z;
                xs[k4 * 4 + 3][r] = v.w;
            }
#pragma unroll
            for (int it = 0; it < 4; it++) {
                int f  = tid + it * 256;
                int kr = f >> 5;
                int c4 = f & 31;
                *(float4*)&ws[kr][c4 * 4] =
                    *(const float4*)(W1 + (size_t)(kb + kr) * DOUT + c4 * 4);
            }
            __syncthreads();
#pragma unroll
            for (int kk = 0; kk < 32; kk++) {
                float4 xa = *(float4*)&xs[kk][tr * 8];
                float4 xb = *(float4*)&xs[kk][tr * 8 + 4];
                float4 w  = *(float4*)&ws[kk][tc * 4];
                float xr[8] = {xa.x, xa.y, xa.z, xa.w, xb.x, xb.y, xb.z, xb.w};
                float wr[4] = {w.x, w.y, w.z, w.w};
#pragma unroll
                for (int r = 0; r < 8; r++)
#pragma unroll
                    for (int c = 0; c < 4; c++)
                        acc[r][c] = fmaf(xr[r], wr[c], acc[r][c]);
            }
            __syncthreads();
        }
        {
            float bb[4];
#pragma unroll
            for (int c = 0; c < 4; c++) bb[c] = b1[tc * 4 + c];
#pragma unroll
            for (int r = 0; r < 8; r++)
#pragma unroll
                for (int c = 0; c < 4; c++) {
                    float v = acc[r][c] + bb[c];
                    h1T[tc * 4 + c][tr * 8 + r] = fmaxf(v, 0.f);
                    acc[r][c] = 0.f;
                }
        }
        __syncthreads();

        for (int kb = 0; kb < DOUT; kb += 32) {
#pragma unroll
            for (int it = 0; it < 4; it++) {
                int f  = tid + it * 256;
                int kr = f >> 5;
                int c4 = f & 31;
                *(float4*)&ws[kr][c4 * 4] =
                    *(const float4*)(W2 + (size_t)(kb + kr) * DOUT + c4 * 4);
            }
            __syncthreads();
#pragma unroll
            for (int kk = 0; kk < 32; kk++) {
                float4 xa = *(float4*)&h1T[kb + kk][tr * 8];
                float4 xb = *(float4*)&h1T[kb + kk][tr * 8 + 4];
                float4 w  = *(float4*)&ws[kk][tc * 4];
                float xr[8] = {xa.x, xa.y, xa.z, xa.w, xb.x, xb.y, xb.z, xb.w};
                float wr[4] = {w.x, w.y, w.z, w.w};
#pragma unroll
                for (int r = 0; r < 8; r++)
#pragma unroll
                    for (int c = 0; c < 4; c++)
                        acc[r][c] = fmaf(xr[r], wr[c], acc[r][c]);
            }
            __syncthreads();
        }
        {
            float bb[4];
#pragma unroll
            for (int c = 0; c < 4; c++) bb[c] = b2[tc * 4 + c];
#pragma unroll
            for (int r = 0; r < 8; r++) {
                float x0 = acc[r][0] + bb[0];
                float x1 = acc[r][1] + bb[1];
                float x2 = acc[r][2] + bb[2];
                float x3 = acc[r][3] + bb[3];
                uint2 o;
                o.x = pack_bf16x2(x0, x1);
                o.y = pack_bf16x2(x2, x3);
                *(uint2*)(g_h + (rowBase + tr * 8 + r) * DOUT + tc * 4) = o;
            }
        }
        __syncthreads();
    }
#endif
}

// ---------------------------------------------------------------------------
// Gather kernel, n-PAIR sliced: blockIdx.x = n2 * 4096 + u_block, n2 in 0..3.
// Pass n2 covers n in {2*n2, 2*n2+1}: live g_h slice = 8 MB (L2 resident),
// and up/out rows for (u,2p),(u,2p+1) form contiguous 1 KB chunks.
// 8 lanes per row, 16 bf16 (32B) per lane; 16 u x 2 n per block.
// ---------------------------------------------------------------------------
__global__ __launch_bounds__(256)
void gather_add_kernel(const float* __restrict__ up,
                       const int*   __restrict__ idx,
                       float*       __restrict__ out)
{
    const int n2     = blockIdx.x >> 12;            // 0..3
    const int ublock = blockIdx.x & 4095;           // 0..4095
    const int lane   = threadIdx.x & 7;             // 16-bf16 chunk id
    const int nsub   = (threadIdx.x >> 3) & 1;      // 0/1
    const int n      = n2 * 2 + nsub;
    const long u     = (long)ublock * 16 + (threadIdx.x >> 4);
    const long row   = u * NNm + n;                 // output row (u,n)

    const int* ip = idx + row * 3;
    int i0 = __ldg(ip + 0);
    int i1 = __ldg(ip + 1);
    int i2 = __ldg(ip + 2);

    const __nv_bfloat16* p0 = g_h + (size_t)(i0 * NNm + n) * DOUT + lane * 16;
    const __nv_bfloat16* p1 = g_h + (size_t)(i1 * NNm + n) * DOUT + lane * 16;
    const __nv_bfloat16* p2 = g_h + (size_t)(i2 * NNm + n) * DOUT + lane * 16;

    uint64_t ga[4], gb[4], gc[4];
    ldg_evl4x64(p0, ga);
    ldg_evl4x64(p1, gb);
    ldg_evl4x64(p2, gc);

    const float4* upp = (const float4*)(up + row * DOUT + lane * 16);
    float4 u4[4];
    u4[0] = __ldcs(upp + 0);
    u4[1] = __ldcs(upp + 1);
    u4[2] = __ldcs(upp + 2);
    u4[3] = __ldcs(upp + 3);

    const float inv3 = 1.0f / 3.0f;
    float4 o[4];
    float* uo = (float*)u4;
    float* oo = (float*)o;
#pragma unroll
    for (int q = 0; q < 4; q++) {
#pragma unroll
        for (int hw = 0; hw < 2; hw++) {
            uint32_t wa = (uint32_t)(ga[q] >> (hw * 32));
            uint32_t wb = (uint32_t)(gb[q] >> (hw * 32));
            uint32_t wc = (uint32_t)(gc[q] >> (hw * 32));
            float a0 = __uint_as_float(wa << 16), a1 = __uint_as_float(wa & 0xFFFF0000u);
            float b0 = __uint_as_float(wb << 16), b1 = __uint_as_float(wb & 0xFFFF0000u);
            float c0 = __uint_as_float(wc << 16), c1 = __uint_as_float(wc & 0xFFFF0000u);
            int e = q * 4 + hw * 2;
            oo[e + 0] = fmaf(a0 + b0 + c0, inv3, uo[e + 0]);
            oo[e + 1] = fmaf(a1 + b1 + c1, inv3, uo[e + 1]);
        }
    }

    float4* op = (float4*)(out + row * DOUT + lane * 16);
    __stcs(op + 0, o[0]);
    __stcs(op + 1, o[1]);
    __stcs(op + 2, o[2]);
    __stcs(op + 3, o[3]);
}

// ---------------------------------------------------------------------------
// Launch: inputs = down_features, up_features, idx, W1, b1, W2, b2
// ---------------------------------------------------------------------------
extern "C" void kernel_launch(void* const* d_in, const int* in_sizes, int n_in,
                              void* d_out, int out_size)
{
    const float* down = (const float*)d_in[0];
    const float* up   = (const float*)d_in[1];
    const int*   idx  = (const int*)  d_in[2];
    const float* W1   = (const float*)d_in[3];
    const float* b1   = (const float*)d_in[4];
    const float* W2   = (const float*)d_in[5];
    const float* b2   = (const float*)d_in[6];
    float* out = (float*)d_out;

    static int smem_set = 0;
    if (!smem_set) {
        cudaFuncSetAttribute(mlp_kernel,
                             cudaFuncAttributeMaxDynamicSharedMemorySize, SMEM_TOTAL);
        smem_set = 1;
    }

    // 1. Split weights into bf16 hi/lo (coalesced reads)
    wsplit_kernel<<<192, 256>>>(W1, W2);

    // 2. MLP -> g_h bf16 (128 rows per CTA, grid 1024)
    mlp_kernel<<<M_ROWS / 128, 256, SMEM_TOTAL>>>(down, W1, b1, W2, b2);

    // 3. Gather + mean + add, n-pair sliced (4 passes x 4096 blocks)
    gather_add_kernel<<<4 * 4096, 256>>>(up, idx, out);
}

// round 12
// speedup vs baseline: 1.2264x; 1.0196x over previous
#include <cuda_runtime.h>
#include <cuda_bf16.h>
#include <cstdint>

// Problem constants
#define LDm   16384
#define LUm   65536
#define NNm   8
#define DIN   256
#define DOUT  128
#define M_ROWS (LDm * NNm)            // 131072 MLP rows
#define OUT_ROWS ((long)LUm * NNm)    // 524288 output rows

// Arch-specific (sm_103a/sm_100a) pass?
#if defined(__CUDA_ARCH__) && (defined(__CUDA_ARCH_FEAT_SM103_ALL) || \
    defined(__CUDA_ARCH_FEAT_SM100_ALL) || \
    (defined(__CUDA_ARCH_SPECIFIC__) && (__CUDA_ARCH_SPECIFIC__ >= 1000)))
#define HAS_TCGEN05 1
#else
#define HAS_TCGEN05 0
#endif

// Scratch: h = relu(x@W1+b1)@W2+b2  [LD, N, D_OUT] in bf16 (32 MB)
__device__ __align__(128) __nv_bfloat16 g_h[(size_t)M_ROWS * DOUT];
// Precomputed bf16 hi/lo splits of W1^T, W2^T (B operands, N x K, K-major)
__device__ __align__(16) __nv_bfloat16 g_w1t_hi[DOUT * DIN];
__device__ __align__(16) __nv_bfloat16 g_w1t_lo[DOUT * DIN];
__device__ __align__(16) __nv_bfloat16 g_w2t_hi[DOUT * DOUT];
__device__ __align__(16) __nv_bfloat16 g_w2t_lo[DOUT * DOUT];

#define SMEM_TOTAL 67584

// ---------------------------------------------------------------------------
// Pre-kernel: split W1^T / W2^T into bf16 hi/lo (coalesced reads)
// ---------------------------------------------------------------------------
__global__ void wsplit_kernel(const float* __restrict__ W1,
                              const float* __restrict__ W2)
{
    int t = blockIdx.x * blockDim.x + threadIdx.x;
    if (t < DIN * DOUT) {                   // W1: t = k*128 + n (coalesced read)
        int k = t >> 7, n = t & 127;
        float x = W1[t];
        uint32_t b = __float_as_uint(x);
        float hf = __uint_as_float(b & 0xFFFF0000u);
        g_w1t_hi[n * DIN + k] = __ushort_as_bfloat16((unsigned short)(b >> 16));
        g_w1t_lo[n * DIN + k] = __float2bfloat16(x - hf);
    } else {
        int t2 = t - DIN * DOUT;
        if (t2 < DOUT * DOUT) {             // W2: t2 = k*128 + n
            int k = t2 >> 7, n = t2 & 127;
            float x = W2[t2];
            uint32_t b = __float_as_uint(x);
            float hf = __uint_as_float(b & 0xFFFF0000u);
            g_w2t_hi[n * DOUT + k] = __ushort_as_bfloat16((unsigned short)(b >> 16));
            g_w2t_lo[n * DOUT + k] = __float2bfloat16(x - hf);
        }
    }
}

#if HAS_TCGEN05
// ---------------------------------------------------------------------------
// PTX helpers
// ---------------------------------------------------------------------------
__device__ __forceinline__ uint32_t smem_u32(const void* p) {
    uint32_t a;
    asm("{ .reg .u64 t; cvta.to.shared.u64 t, %1; cvt.u32.u64 %0, t; }"
        : "=r"(a) : "l"(p));
    return a;
}
__device__ __forceinline__ uint32_t elect_one() {
    uint32_t p;
    asm volatile("{ .reg .pred p; elect.sync _|p, 0xFFFFFFFF; selp.b32 %0,1,0,p; }"
                 : "=r"(p));
    return p;
}
#define TCG_ALLOC(sm, n)  asm volatile("tcgen05.alloc.cta_group::1.sync.aligned.shared::cta.b32 [%0], %1;" :: "r"(sm), "r"((uint32_t)(n)) : "memory")
#define TCG_DEALLOC(t, n) asm volatile("tcgen05.dealloc.cta_group::1.sync.aligned.b32 %0, %1;" :: "r"(t), "r"((uint32_t)(n)))
#define TCG_RELINQ()      asm volatile("tcgen05.relinquish_alloc_permit.cta_group::1.sync.aligned;")
#define TCG_COMMIT(mb)    asm volatile("tcgen05.commit.cta_group::1.mbarrier::arrive::one.shared::cluster.b64 [%0];" :: "r"(mb) : "memory")
#define TCG_WAIT_LD()     asm volatile("tcgen05.wait::ld.sync.aligned;" ::: "memory")
#define TCG_FENCE_BEFORE() asm volatile("tcgen05.fence::before_thread_sync;" ::: "memory")
#define TCG_FENCE_AFTER()  asm volatile("tcgen05.fence::after_thread_sync;" ::: "memory")
#define FENCE_ASYNC_SHARED() asm volatile("fence.proxy.async.shared::cta;" ::: "memory")
#define MBAR_INIT(mb, c)  asm volatile("mbarrier.init.shared.b64 [%0], %1;" :: "r"(mb), "r"((uint32_t)(c)) : "memory")
#define MBAR_INVAL(mb)    asm volatile("mbarrier.inval.shared.b64 [%0];" :: "r"(mb) : "memory")

__device__ __forceinline__ void mbar_wait(uint32_t mb, uint32_t parity) {
    asm volatile(
        "{\n\t.reg .pred P1;\n\t"
        "WAIT_LOOP_%=:\n\t"
        "mbarrier.try_wait.parity.acquire.cta.shared::cta.b64 P1, [%0], %1, 0x989680;\n\t"
        "@P1 bra.uni WAIT_DONE_%=;\n\t"
        "bra.uni WAIT_LOOP_%=;\n\t"
        "WAIT_DONE_%=:\n\t}"
        :: "r"(mb), "r"(parity) : "memory");
}

__device__ __forceinline__ void mma_ss(uint32_t d, uint64_t ad, uint64_t bd,
                                       uint32_t idesc, uint32_t en) {
    asm volatile(
        "{\n\t.reg .pred p;\n\tsetp.ne.u32 p, %4, 0;\n\t"
        "tcgen05.mma.cta_group::1.kind::f16 [%0], %1, %2, %3, {%5,%5,%5,%5}, p;\n\t}"
        :: "r"(d), "l"(ad), "l"(bd), "r"(idesc), "r"(en), "r"(0u) : "memory");
}

#define LDTM_X16(r, a) \
    asm volatile("tcgen05.ld.sync.aligned.32x32b.x16.b32 " \
        "{%0,%1,%2,%3,%4,%5,%6,%7,%8,%9,%10,%11,%12,%13,%14,%15}, [%16];" \
        : "=r"((r)[0]),"=r"((r)[1]),"=r"((r)[2]),"=r"((r)[3]), \
          "=r"((r)[4]),"=r"((r)[5]),"=r"((r)[6]),"=r"((r)[7]), \
          "=r"((r)[8]),"=r"((r)[9]),"=r"((r)[10]),"=r"((r)[11]), \
          "=r"((r)[12]),"=r"((r)[13]),"=r"((r)[14]),"=r"((r)[15]) : "r"(a))

#define LDTM_X32(r, a) \
    asm volatile("tcgen05.ld.sync.aligned.32x32b.x32.b32 " \
        "{%0,%1,%2,%3,%4,%5,%6,%7,%8,%9,%10,%11,%12,%13,%14,%15," \
        "%16,%17,%18,%19,%20,%21,%22,%23,%24,%25,%26,%27,%28,%29,%30,%31}, [%32];" \
        : "=r"((r)[0]),"=r"((r)[1]),"=r"((r)[2]),"=r"((r)[3]), \
          "=r"((r)[4]),"=r"((r)[5]),"=r"((r)[6]),"=r"((r)[7]), \
          "=r"((r)[8]),"=r"((r)[9]),"=r"((r)[10]),"=r"((r)[11]), \
          "=r"((r)[12]),"=r"((r)[13]),"=r"((r)[14]),"=r"((r)[15]), \
          "=r"((r)[16]),"=r"((r)[17]),"=r"((r)[18]),"=r"((r)[19]), \
          "=r"((r)[20]),"=r"((r)[21]),"=r"((r)[22]),"=r"((r)[23]), \
          "=r"((r)[24]),"=r"((r)[25]),"=r"((r)[26]),"=r"((r)[27]), \
          "=r"((r)[28]),"=r"((r)[29]),"=r"((r)[30]),"=r"((r)[31]) : "r"(a))

__device__ __forceinline__ uint64_t mk_desc(uint32_t addr) {
    return ((uint64_t)2 << 61) | ((uint64_t)1 << 46) | ((uint64_t)64 << 32) |
           ((uint64_t)1 << 16) | (uint64_t)((addr >> 4) & 0x3FFF);
}
#endif // HAS_TCGEN05

#define SWZ(o) ((o) ^ (((o) >> 3) & 0x70))

// Truncation split: hi = top-16-bits of fp32, lo = rn_bf16(x - hi)
__device__ __forceinline__ void split2(float x0, float x1, uint32_t& hi, uint32_t& lo) {
    uint32_t b0 = __float_as_uint(x0), b1 = __float_as_uint(x1);
    hi = __byte_perm(b0, b1, 0x7632);
    float l0 = x0 - __uint_as_float(b0 & 0xFFFF0000u);
    float l1 = x1 - __uint_as_float(b1 & 0xFFFF0000u);
    asm("cvt.rn.bf16x2.f32 %0, %1, %2;" : "=r"(lo) : "f"(l1), "f"(l0));
}

// pack two fp32 into bf16x2 word (lo half = x0)
__device__ __forceinline__ uint32_t pack_bf16x2(float x0, float x1) {
    uint32_t w;
    asm("cvt.rn.bf16x2.f32 %0, %1, %2;" : "=r"(w) : "f"(x1), "f"(x0));
    return w;
}

// 256-bit evict_last global load: 4 x u64 (= 16 bf16)
__device__ __forceinline__ void ldg_evl4x64(const void* p, uint64_t* v) {
    asm volatile("ld.global.nc.L2::evict_last.v4.b64 {%0,%1,%2,%3}, [%4];"
        : "=l"(v[0]), "=l"(v[1]), "=l"(v[2]), "=l"(v[3]) : "l"(p));
}
// 256-bit evict_last global store: 4 x u64
__device__ __forceinline__ void stg_evl4x64(void* p, const uint64_t* v) {
    asm volatile("st.global.L2::evict_last.v4.b64 [%0], {%1,%2,%3,%4};"
        :: "l"(p), "l"(v[0]), "l"(v[1]), "l"(v[2]), "l"(v[3]) : "memory");
}

// ---------------------------------------------------------------------------
// MLP kernel — 128 rows/CTA, grid 1024, bf16 epilogue.
// GEMM1 X loads are register-prefetched one round ahead to hide DRAM latency
// behind B-fill + sync + MMA + mbar-wait.
// ---------------------------------------------------------------------------
__global__ __launch_bounds__(256, 2)
void mlp_kernel(const float* __restrict__ X,
                const float* __restrict__ W1,
                const float* __restrict__ b1,
                const float* __restrict__ W2,
                const float* __restrict__ b2)
{
    extern __shared__ char smem[];
#if HAS_TCGEN05
#define SM_AHI 1024
#define SM_ALO 17408
#define SM_BHI 33792
#define SM_BLO 50176
#define SM_B1  66560
#define SM_B2  67072
    const uint32_t sb  = smem_u32(smem);
    const int tid = threadIdx.x, wid = tid >> 5, lid = tid & 31;
    const long rowBase = (long)blockIdx.x * 128;

    float* b1s = (float*)(smem + SM_B1);
    float* b2s = (float*)(smem + SM_B2);

    if (wid == 0) { TCG_ALLOC(sb + 0, 256); TCG_RELINQ(); }
    if (tid == 0) MBAR_INIT(sb + 8, 1);
    if (tid < 128) { b1s[tid] = b1[tid]; b2s[tid] = b2[tid]; }
    __syncthreads();

    uint32_t tmem;
    asm volatile("ld.shared.b32 %0, [%1];" : "=r"(tmem) : "r"(sb + 0));

    const uint32_t idesc = (1u << 4) | (1u << 7) | (1u << 10) |
                           ((DOUT / 8) << 17) | ((128 / 16) << 24);
    const uint64_t adhi = mk_desc(sb + SM_AHI);
    const uint64_t adlo = mk_desc(sb + SM_ALO);
    const uint64_t bdhi = mk_desc(sb + SM_BHI);
    const uint64_t bdlo = mk_desc(sb + SM_BLO);

    uint32_t parity = 0;

    // per-thread X tile coords (4 iterations x 2 float4)
    const int xr  = tid >> 3;          // rows handled: xr, xr+32, xr+64, xr+96? No:
    // iteration it covers f = it*256+tid -> r = f>>3 = it*32 + (tid>>3), c8 = tid&7
    const int c8  = tid & 7;
    const float* Xrow = X + rowBase * DIN + (size_t)0;

    // -------- prefetch round 0 into registers --------
    float4 pa[4], pb[4];
#pragma unroll
    for (int it = 0; it < 4; it++) {
        int r = it * 32 + xr;
        const float4* src = (const float4*)(Xrow + (size_t)r * DIN + 0 * 64 + c8 * 8);
        pa[it] = src[0];
        pb[it] = src[1];
    }

    // ================= GEMM1: 4 K-chunks of 64 (X prefetched) =================
    for (int kb = 0; kb < 4; kb++) {
        // 1. convert prefetched regs -> A smem (previous mbar_wait already done)
#pragma unroll
        for (int it = 0; it < 4; it++) {
            int r = it * 32 + xr;
            uint32_t h0, l0, h1, l1, h2, l2, h3, l3;
            split2(pa[it].x, pa[it].y, h0, l0);
            split2(pa[it].z, pa[it].w, h1, l1);
            split2(pb[it].x, pb[it].y, h2, l2);
            split2(pb[it].z, pb[it].w, h3, l3);
            uint32_t off = SWZ((uint32_t)(r * 128 + c8 * 16));
            *(uint4*)(smem + SM_AHI + off) = make_uint4(h0, h1, h2, h3);
            *(uint4*)(smem + SM_ALO + off) = make_uint4(l0, l1, l2, l3);
        }
        // 2. issue prefetch for round kb+1 (latency hidden behind rest of round)
        if (kb < 3) {
#pragma unroll
            for (int it = 0; it < 4; it++) {
                int r = it * 32 + xr;
                const float4* src = (const float4*)(Xrow + (size_t)r * DIN + (kb + 1) * 64 + c8 * 8);
                pa[it] = src[0];
                pb[it] = src[1];
            }
        }
        // 3. B-fill (W1^T chunk hi+lo)
#pragma unroll
        for (int it = 0; it < 8; it++) {
            int f = it * 256 + tid;
            int g = f & 1023;
            int n = g >> 3, c16 = g & 7;
            const __nv_bfloat16* wsrc = (f < 1024) ? g_w1t_hi : g_w1t_lo;
            uint4 v = *(const uint4*)(wsrc + (size_t)n * DIN + kb * 64 + c16 * 8);
            uint32_t dst = ((f < 1024) ? SM_BHI : SM_BLO) + SWZ((uint32_t)(n * 128 + c16 * 16));
            *(uint4*)(smem + dst) = v;
        }
        __syncthreads();

        if (wid == 0) {
            FENCE_ASYNC_SHARED();
            if (elect_one()) {
#pragma unroll
                for (int ks = 0; ks < 4; ks++)
                    mma_ss(tmem, adhi + ks * 2, bdhi + ks * 2, idesc, (kb > 0) || (ks > 0));
#pragma unroll
                for (int ks = 0; ks < 4; ks++)
                    mma_ss(tmem, adhi + ks * 2, bdlo + ks * 2, idesc, 1);
#pragma unroll
                for (int ks = 0; ks < 4; ks++)
                    mma_ss(tmem, adlo + ks * 2, bdhi + ks * 2, idesc, 1);
                TCG_COMMIT(sb + 8);
            }
        }
        mbar_wait(sb + 8, parity); parity ^= 1;
        TCG_FENCE_AFTER();
    }

    // ================= GEMM2: 2 K-chunks of 64 =================
    for (int c2 = 0; c2 < 2; c2++) {
        if (wid < 4) {
            int row = wid * 32 + lid;
#pragma unroll
            for (int part = 0; part < 4; part++) {
                uint32_t r16[16];
                LDTM_X16(r16, tmem + c2 * 64 + part * 16);
                TCG_WAIT_LD();
#pragma unroll
                for (int grp = 0; grp < 2; grp++) {
                    uint32_t hs[4], ls[4];
#pragma unroll
                    for (int q = 0; q < 4; q++) {
                        int c = grp * 8 + q * 2;
                        float x0 = __uint_as_float(r16[c])     + b1s[c2 * 64 + part * 16 + c];
                        float x1 = __uint_as_float(r16[c + 1]) + b1s[c2 * 64 + part * 16 + c + 1];
                        x0 = fmaxf(x0, 0.f);
                        x1 = fmaxf(x1, 0.f);
                        split2(x0, x1, hs[q], ls[q]);
                    }
                    uint32_t off = SWZ((uint32_t)(row * 128 + (part * 16 + grp * 8) * 2));
                    *(uint4*)(smem + SM_AHI + off) = make_uint4(hs[0], hs[1], hs[2], hs[3]);
                    *(uint4*)(smem + SM_ALO + off) = make_uint4(ls[0], ls[1], ls[2], ls[3]);
                }
            }
        } else {
            int t2 = tid - 128;
#pragma unroll
            for (int it = 0; it < 16; it++) {
                int f = it * 128 + t2;
                int g = f & 1023;
                int n = g >> 3, c16 = g & 7;
                const __nv_bfloat16* wsrc = (f < 1024) ? g_w2t_hi : g_w2t_lo;
                uint4 v = *(const uint4*)(wsrc + (size_t)n * DOUT + c2 * 64 + c16 * 8);
                uint32_t dst = ((f < 1024) ? SM_BHI : SM_BLO) + SWZ((uint32_t)(n * 128 + c16 * 16));
                *(uint4*)(smem + dst) = v;
            }
        }
        __syncthreads();

        if (wid == 0) {
            FENCE_ASYNC_SHARED();
            if (elect_one()) {
#pragma unroll
                for (int ks = 0; ks < 4; ks++)
                    mma_ss(tmem + 128, adhi + ks * 2, bdhi + ks * 2, idesc, (c2 > 0) || (ks > 0));
#pragma unroll
                for (int ks = 0; ks < 4; ks++)
                    mma_ss(tmem + 128, adhi + ks * 2, bdlo + ks * 2, idesc, 1);
#pragma unroll
                for (int ks = 0; ks < 4; ks++)
                    mma_ss(tmem + 128, adlo + ks * 2, bdhi + ks * 2, idesc, 1);
                TCG_COMMIT(sb + 8);
            }
        }
        mbar_wait(sb + 8, parity); parity ^= 1;
        TCG_FENCE_AFTER();
    }

    // ================= Epilogue: bf16(D2 + b2) -> g_h =================
    if (wid < 4) {
        int row = wid * 32 + lid;
        __nv_bfloat16* dst = g_h + (size_t)(rowBase + row) * DOUT;
#pragma unroll
        for (int grp = 0; grp < 4; grp++) {
            uint32_t r32[32];
            LDTM_X32(r32, tmem + 128 + grp * 32);
            TCG_WAIT_LD();
            uint64_t w64[8];
#pragma unroll
            for (int q = 0; q < 8; q++) {
                float x0 = __uint_as_float(r32[q * 4 + 0]) + b2s[grp * 32 + q * 4 + 0];
                float x1 = __uint_as_float(r32[q * 4 + 1]) + b2s[grp * 32 + q * 4 + 1];
                float x2 = __uint_as_float(r32[q * 4 + 2]) + b2s[grp * 32 + q * 4 + 2];
                float x3 = __uint_as_float(r32[q * 4 + 3]) + b2s[grp * 32 + q * 4 + 3];
                uint32_t wlo = pack_bf16x2(x0, x1);
                uint32_t whi = pack_bf16x2(x2, x3);
                w64[q] = (uint64_t)wlo | ((uint64_t)whi << 32);
            }
            stg_evl4x64(dst + grp * 32,      w64);
            stg_evl4x64(dst + grp * 32 + 16, w64 + 4);
        }
        TCG_FENCE_BEFORE();
    }
    __syncthreads();
    if (tid == 0) MBAR_INVAL(sb + 8);
    __syncthreads();
    if (wid == 0) TCG_DEALLOC(tmem, 256);

#else  // ===================== fp32 FFMA fallback =====================
    float (*xs)[68]   = (float (*)[68])(smem);
    float (*ws)[128]  = (float (*)[128])(smem + 32 * 68 * 4);
    float (*h1T)[68]  = (float (*)[68])(smem + 32 * 68 * 4 + 32 * 128 * 4);

    const int tid = threadIdx.x;
    const int tr  = tid >> 5;
    const int tc  = tid & 31;

    for (int half = 0; half < 2; half++) {
        const long rowBase = (long)blockIdx.x * 128 + half * 64;
        float acc[8][4];
#pragma unroll
        for (int r = 0; r < 8; r++)
#pragma unroll
            for (int c = 0; c < 4; c++) acc[r][c] = 0.f;

        for (int kb = 0; kb < DIN; kb += 32) {
#pragma unroll
            for (int it = 0; it < 2; it++) {
                int f = tid + it * 256;
                int r  = f >> 3;
                int k4 = f & 7;
                float4 v = *(const float4*)(X + (rowBase + r) * DIN + kb + k4 * 4);
                xs[k4 * 4 + 0][r] = v.x;
                xs[k4 * 4 + 1][r] = v.y;
                xs[k4 * 4 + 2][r] = v.z;
                xs[k4 * 4 + 3][r] = v.w;
            }
#pragma unroll
            for (int it = 0; it < 4; it++) {
                int f  = tid + it * 256;
                int kr = f >> 5;
                int c4 = f & 31;
                *(float4*)&ws[kr][c4 * 4] =
                    *(const float4*)(W1 + (size_t)(kb + kr) * DOUT + c4 * 4);
            }
            __syncthreads();
#pragma unroll
            for (int kk = 0; kk < 32; kk++) {
                float4 xa = *(float4*)&xs[kk][tr * 8];
                float4 xb = *(float4*)&xs[kk][tr * 8 + 4];
                float4 w  = *(float4*)&ws[kk][tc * 4];
                float xr8[8] = {xa.x, xa.y, xa.z, xa.w, xb.x, xb.y, xb.z, xb.w};
                float wr[4] = {w.x, w.y, w.z, w.w};
#pragma unroll
                for (int r = 0; r < 8; r++)
#pragma unroll
                    for (int c = 0; c < 4; c++)
                        acc[r][c] = fmaf(xr8[r], wr[c], acc[r][c]);
            }
            __syncthreads();
        }
        {
            float bb[4];
#pragma unroll
            for (int c = 0; c < 4; c++) bb[c] = b1[tc * 4 + c];
#pragma unroll
            for (int r = 0; r < 8; r++)
#pragma unroll
                for (int c = 0; c < 4; c++) {
                    float v = acc[r][c] + bb[c];
                    h1T[tc * 4 + c][tr * 8 + r] = fmaxf(v, 0.f);
                    acc[r][c] = 0.f;
                }
        }
        __syncthreads();

        for (int kb = 0; kb < DOUT; kb += 32) {
#pragma unroll
            for (int it = 0; it < 4; it++) {
                int f  = tid + it * 256;
                int kr = f >> 5;
                int c4 = f & 31;
                *(float4*)&ws[kr][c4 * 4] =
                    *(const float4*)(W2 + (size_t)(kb + kr) * DOUT + c4 * 4);
            }
            __syncthreads();
#pragma unroll
            for (int kk = 0; kk < 32; kk++) {
                float4 xa = *(float4*)&h1T[kb + kk][tr * 8];
                float4 xb = *(float4*)&h1T[kb + kk][tr * 8 + 4];
                float4 w  = *(float4*)&ws[kk][tc * 4];
                float xr8[8] = {xa.x, xa.y, xa.z, xa.w, xb.x, xb.y, xb.z, xb.w};
                float wr[4] = {w.x, w.y, w.z, w.w};
#pragma unroll
                for (int r = 0; r < 8; r++)
#pragma unroll
                    for (int c = 0; c < 4; c++)
                        acc[r][c] = fmaf(xr8[r], wr[c], acc[r][c]);
            }
            __syncthreads();
        }
        {
            float bb[4];
#pragma unroll
            for (int c = 0; c < 4; c++) bb[c] = b2[tc * 4 + c];
#pragma unroll
            for (int r = 0; r < 8; r++) {
                float x0 = acc[r][0] + bb[0];
                float x1 = acc[r][1] + bb[1];
                float x2 = acc[r][2] + bb[2];
                float x3 = acc[r][3] + bb[3];
                uint2 o;
                o.x = pack_bf16x2(x0, x1);
                o.y = pack_bf16x2(x2, x3);
                *(uint2*)(g_h + (rowBase + tr * 8 + r) * DOUT + tc * 4) = o;
            }
        }
        __syncthreads();
    }
#endif
}

// ---------------------------------------------------------------------------
// Gather kernel, n-PAIR sliced (R11 version, ~at DRAM limit)
// ---------------------------------------------------------------------------
__global__ __launch_bounds__(256)
void gather_add_kernel(const float* __restrict__ up,
                       const int*   __restrict__ idx,
                       float*       __restrict__ out)
{
    const int n2     = blockIdx.x >> 12;            // 0..3
    const int ublock = blockIdx.x & 4095;           // 0..4095
    const int lane   = threadIdx.x & 7;             // 16-bf16 chunk id
    const int nsub   = (threadIdx.x >> 3) & 1;      // 0/1
    const int n      = n2 * 2 + nsub;
    const long u     = (long)ublock * 16 + (threadIdx.x >> 4);
    const long row   = u * NNm + n;                 // output row (u,n)

    const int* ip = idx + row * 3;
    int i0 = __ldg(ip + 0);
    int i1 = __ldg(ip + 1);
    int i2 = __ldg(ip + 2);

    const __nv_bfloat16* p0 = g_h + (size_t)(i0 * NNm + n) * DOUT + lane * 16;
    const __nv_bfloat16* p1 = g_h + (size_t)(i1 * NNm + n) * DOUT + lane * 16;
    const __nv_bfloat16* p2 = g_h + (size_t)(i2 * NNm + n) * DOUT + lane * 16;

    uint64_t ga[4], gb[4], gc[4];
    ldg_evl4x64(p0, ga);
    ldg_evl4x64(p1, gb);
    ldg_evl4x64(p2, gc);

    const float4* upp = (const float4*)(up + row * DOUT + lane * 16);
    float4 u4[4];
    u4[0] = __ldcs(upp + 0);
    u4[1] = __ldcs(upp + 1);
    u4[2] = __ldcs(upp + 2);
    u4[3] = __ldcs(upp + 3);

    const float inv3 = 1.0f / 3.0f;
    float4 o[4];
    float* uo = (float*)u4;
    float* oo = (float*)o;
#pragma unroll
    for (int q = 0; q < 4; q++) {
#pragma unroll
        for (int hw = 0; hw < 2; hw++) {
            uint32_t wa = (uint32_t)(ga[q] >> (hw * 32));
            uint32_t wb = (uint32_t)(gb[q] >> (hw * 32));
            uint32_t wc = (uint32_t)(gc[q] >> (hw * 32));
            float a0 = __uint_as_float(wa << 16), a1 = __uint_as_float(wa & 0xFFFF0000u);
            float b0 = __uint_as_float(wb << 16), b1 = __uint_as_float(wb & 0xFFFF0000u);
            float c0 = __uint_as_float(wc << 16), c1 = __uint_as_float(wc & 0xFFFF0000u);
            int e = q * 4 + hw * 2;
            oo[e + 0] = fmaf(a0 + b0 + c0, inv3, uo[e + 0]);
            oo[e + 1] = fmaf(a1 + b1 + c1, inv3, uo[e + 1]);
        }
    }

    float4* op = (float4*)(out + row * DOUT + lane * 16);
    __stcs(op + 0, o[0]);
    __stcs(op + 1, o[1]);
    __stcs(op + 2, o[2]);
    __stcs(op + 3, o[3]);
}

// ---------------------------------------------------------------------------
// Launch: inputs = down_features, up_features, idx, W1, b1, W2, b2
// ---------------------------------------------------------------------------
extern "C" void kernel_launch(void* const* d_in, const int* in_sizes, int n_in,
                              void* d_out, int out_size)
{
    const float* down = (const float*)d_in[0];
    const float* up   = (const float*)d_in[1];
    const int*   idx  = (const int*)  d_in[2];
    const float* W1   = (const float*)d_in[3];
    const float* b1   = (const float*)d_in[4];
    const float* W2   = (const float*)d_in[5];
    const float* b2   = (const float*)d_in[6];
    float* out = (float*)d_out;

    static int smem_set = 0;
    if (!smem_set) {
        cudaFuncSetAttribute(mlp_kernel,
                             cudaFuncAttributeMaxDynamicSharedMemorySize, SMEM_TOTAL);
        smem_set = 1;
    }

    // 1. Split weights into bf16 hi/lo
    wsplit_kernel<<<192, 256>>>(W1, W2);

    // 2. MLP -> g_h bf16 (128 rows per CTA, grid 1024, X register-prefetched)
    mlp_kernel<<<M_ROWS / 128, 256, SMEM_TOTAL>>>(down, W1, b1, W2, b2);

    // 3. Gather + mean + add, n-pair sliced (4 passes x 4096 blocks)
    gather_add_kernel<<<4 * 4096, 256>>>(up, idx, out);
}

// round 13
// speedup vs baseline: 1.2492x; 1.0186x over previous
#include <cuda_runtime.h>
#include <cuda_bf16.h>
#include <cstdint>

// Problem constants
#define LDm   16384
#define LUm   65536
#define NNm   8
#define DIN   256
#define DOUT  128
#define M_ROWS (LDm * NNm)            // 131072 MLP rows
#define OUT_ROWS ((long)LUm * NNm)    // 524288 output rows

// Arch-specific (sm_103a/sm_100a) pass?
#if defined(__CUDA_ARCH__) && (defined(__CUDA_ARCH_FEAT_SM103_ALL) || \
    defined(__CUDA_ARCH_FEAT_SM100_ALL) || \
    (defined(__CUDA_ARCH_SPECIFIC__) && (__CUDA_ARCH_SPECIFIC__ >= 1000)))
#define HAS_TCGEN05 1
#else
#define HAS_TCGEN05 0
#endif

// Scratch: h (bf16, 32 MB)
__device__ __align__(128) __nv_bfloat16 g_h[(size_t)M_ROWS * DOUT];
// Pre-swizzled, chunk-contiguous weight images (SW128 layout, ready for bulk copy)
// W1: 4 chunks x 16 KB ; W2: 2 chunks x 16 KB (each chunk: 128 n-rows x 64 k x bf16)
__device__ __align__(128) __nv_bfloat16 g_w1s_hi[4 * 8192];
__device__ __align__(128) __nv_bfloat16 g_w1s_lo[4 * 8192];
__device__ __align__(128) __nv_bfloat16 g_w2s_hi[2 * 8192];
__device__ __align__(128) __nv_bfloat16 g_w2s_lo[2 * 8192];

#define SMEM_TOTAL 67584
#define SWZ(o) ((o) ^ (((o) >> 3) & 0x70))

// ---------------------------------------------------------------------------
// Pre-kernel: split W1/W2 into bf16 hi/lo, written pre-swizzled per chunk.
// t = k*128 + n (coalesced W reads).
// ---------------------------------------------------------------------------
__global__ void wsplit_kernel(const float* __restrict__ W1,
                              const float* __restrict__ W2)
{
    int t = blockIdx.x * blockDim.x + threadIdx.x;
    if (t < DIN * DOUT) {                   // W1
        int k = t >> 7, n = t & 127;
        int kb = k >> 6, kc = k & 63;
        float x = W1[t];
        uint32_t b = __float_as_uint(x);
        float hf = __uint_as_float(b & 0xFFFF0000u);
        uint32_t off = (uint32_t)kb * 16384 + SWZ((uint32_t)(n * 128 + kc * 2));
        *(__nv_bfloat16*)((char*)g_w1s_hi + off) =
            __ushort_as_bfloat16((unsigned short)(b >> 16));
        *(__nv_bfloat16*)((char*)g_w1s_lo + off) = __float2bfloat16(x - hf);
    } else {
        int t2 = t - DIN * DOUT;
        if (t2 < DOUT * DOUT) {             // W2
            int k = t2 >> 7, n = t2 & 127;
            int kb = k >> 6, kc = k & 63;
            float x = W2[t2];
            uint32_t b = __float_as_uint(x);
            float hf = __uint_as_float(b & 0xFFFF0000u);
            uint32_t off = (uint32_t)kb * 16384 + SWZ((uint32_t)(n * 128 + kc * 2));
            *(__nv_bfloat16*)((char*)g_w2s_hi + off) =
                __ushort_as_bfloat16((unsigned short)(b >> 16));
            *(__nv_bfloat16*)((char*)g_w2s_lo + off) = __float2bfloat16(x - hf);
        }
    }
}

#if HAS_TCGEN05
// ---------------------------------------------------------------------------
// PTX helpers
// ---------------------------------------------------------------------------
__device__ __forceinline__ uint32_t smem_u32(const void* p) {
    uint32_t a;
    asm("{ .reg .u64 t; cvta.to.shared.u64 t, %1; cvt.u32.u64 %0, t; }"
        : "=r"(a) : "l"(p));
    return a;
}
__device__ __forceinline__ uint32_t elect_one() {
    uint32_t p;
    asm volatile("{ .reg .pred p; elect.sync _|p, 0xFFFFFFFF; selp.b32 %0,1,0,p; }"
                 : "=r"(p));
    return p;
}
#define TCG_ALLOC(sm, n)  asm volatile("tcgen05.alloc.cta_group::1.sync.aligned.shared::cta.b32 [%0], %1;" :: "r"(sm), "r"((uint32_t)(n)) : "memory")
#define TCG_DEALLOC(t, n) asm volatile("tcgen05.dealloc.cta_group::1.sync.aligned.b32 %0, %1;" :: "r"(t), "r"((uint32_t)(n)))
#define TCG_RELINQ()      asm volatile("tcgen05.relinquish_alloc_permit.cta_group::1.sync.aligned;")
#define TCG_COMMIT(mb)    asm volatile("tcgen05.commit.cta_group::1.mbarrier::arrive::one.shared::cluster.b64 [%0];" :: "r"(mb) : "memory")
#define TCG_WAIT_LD()     asm volatile("tcgen05.wait::ld.sync.aligned;" ::: "memory")
#define TCG_FENCE_BEFORE() asm volatile("tcgen05.fence::before_thread_sync;" ::: "memory")
#define TCG_FENCE_AFTER()  asm volatile("tcgen05.fence::after_thread_sync;" ::: "memory")
#define FENCE_ASYNC_SHARED() asm volatile("fence.proxy.async.shared::cta;" ::: "memory")
#define MBAR_INIT(mb, c)  asm volatile("mbarrier.init.shared.b64 [%0], %1;" :: "r"(mb), "r"((uint32_t)(c)) : "memory")
#define MBAR_INVAL(mb)    asm volatile("mbarrier.inval.shared.b64 [%0];" :: "r"(mb) : "memory")
#define MBAR_EXPECT_TX(mb, b) asm volatile("mbarrier.arrive.expect_tx.shared.b64 _, [%0], %1;" :: "r"(mb), "r"((uint32_t)(b)) : "memory")

// Bulk async copy global -> shared, completion via mbarrier tx bytes
__device__ __forceinline__ void bulk_cp(uint32_t dst, const void* src,
                                        uint32_t bytes, uint32_t mbar) {
    asm volatile(
        "cp.async.bulk.shared::cluster.global.mbarrier::complete_tx::bytes "
        "[%0], [%1], %2, [%3];"
        :: "r"(dst), "l"(src), "r"(bytes), "r"(mbar) : "memory");
}

__device__ __forceinline__ void mbar_wait(uint32_t mb, uint32_t parity) {
    asm volatile(
        "{\n\t.reg .pred P1;\n\t"
        "WAIT_LOOP_%=:\n\t"
        "mbarrier.try_wait.parity.acquire.cta.shared::cta.b64 P1, [%0], %1, 0x989680;\n\t"
        "@P1 bra.uni WAIT_DONE_%=;\n\t"
        "bra.uni WAIT_LOOP_%=;\n\t"
        "WAIT_DONE_%=:\n\t}"
        :: "r"(mb), "r"(parity) : "memory");
}

__device__ __forceinline__ void mma_ss(uint32_t d, uint64_t ad, uint64_t bd,
                                       uint32_t idesc, uint32_t en) {
    asm volatile(
        "{\n\t.reg .pred p;\n\tsetp.ne.u32 p, %4, 0;\n\t"
        "tcgen05.mma.cta_group::1.kind::f16 [%0], %1, %2, %3, {%5,%5,%5,%5}, p;\n\t}"
        :: "r"(d), "l"(ad), "l"(bd), "r"(idesc), "r"(en), "r"(0u) : "memory");
}

#define LDTM_X16(r, a) \
    asm volatile("tcgen05.ld.sync.aligned.32x32b.x16.b32 " \
        "{%0,%1,%2,%3,%4,%5,%6,%7,%8,%9,%10,%11,%12,%13,%14,%15}, [%16];" \
        : "=r"((r)[0]),"=r"((r)[1]),"=r"((r)[2]),"=r"((r)[3]), \
          "=r"((r)[4]),"=r"((r)[5]),"=r"((r)[6]),"=r"((r)[7]), \
          "=r"((r)[8]),"=r"((r)[9]),"=r"((r)[10]),"=r"((r)[11]), \
          "=r"((r)[12]),"=r"((r)[13]),"=r"((r)[14]),"=r"((r)[15]) : "r"(a))

#define LDTM_X32(r, a) \
    asm volatile("tcgen05.ld.sync.aligned.32x32b.x32.b32 " \
        "{%0,%1,%2,%3,%4,%5,%6,%7,%8,%9,%10,%11,%12,%13,%14,%15," \
        "%16,%17,%18,%19,%20,%21,%22,%23,%24,%25,%26,%27,%28,%29,%30,%31}, [%32];" \
        : "=r"((r)[0]),"=r"((r)[1]),"=r"((r)[2]),"=r"((r)[3]), \
          "=r"((r)[4]),"=r"((r)[5]),"=r"((r)[6]),"=r"((r)[7]), \
          "=r"((r)[8]),"=r"((r)[9]),"=r"((r)[10]),"=r"((r)[11]), \
          "=r"((r)[12]),"=r"((r)[13]),"=r"((r)[14]),"=r"((r)[15]), \
          "=r"((r)[16]),"=r"((r)[17]),"=r"((r)[18]),"=r"((r)[19]), \
          "=r"((r)[20]),"=r"((r)[21]),"=r"((r)[22]),"=r"((r)[23]), \
          "=r"((r)[24]),"=r"((r)[25]),"=r"((r)[26]),"=r"((r)[27]), \
          "=r"((r)[28]),"=r"((r)[29]),"=r"((r)[30]),"=r"((r)[31]) : "r"(a))

__device__ __forceinline__ uint64_t mk_desc(uint32_t addr) {
    return ((uint64_t)2 << 61) | ((uint64_t)1 << 46) | ((uint64_t)64 << 32) |
           ((uint64_t)1 << 16) | (uint64_t)((addr >> 4) & 0x3FFF);
}
#endif // HAS_TCGEN05

// Truncation split: hi = top-16-bits of fp32, lo = rn_bf16(x - hi)
__device__ __forceinline__ void split2(float x0, float x1, uint32_t& hi, uint32_t& lo) {
    uint32_t b0 = __float_as_uint(x0), b1 = __float_as_uint(x1);
    hi = __byte_perm(b0, b1, 0x7632);
    float l0 = x0 - __uint_as_float(b0 & 0xFFFF0000u);
    float l1 = x1 - __uint_as_float(b1 & 0xFFFF0000u);
    asm("cvt.rn.bf16x2.f32 %0, %1, %2;" : "=r"(lo) : "f"(l1), "f"(l0));
}

// pack two fp32 into bf16x2 word (lo half = x0)
__device__ __forceinline__ uint32_t pack_bf16x2(float x0, float x1) {
    uint32_t w;
    asm("cvt.rn.bf16x2.f32 %0, %1, %2;" : "=r"(w) : "f"(x1), "f"(x0));
    return w;
}

// 256-bit evict_last global load/store
__device__ __forceinline__ void ldg_evl4x64(const void* p, uint64_t* v) {
    asm volatile("ld.global.nc.L2::evict_last.v4.b64 {%0,%1,%2,%3}, [%4];"
        : "=l"(v[0]), "=l"(v[1]), "=l"(v[2]), "=l"(v[3]) : "l"(p));
}
__device__ __forceinline__ void stg_evl4x64(void* p, const uint64_t* v) {
    asm volatile("st.global.L2::evict_last.v4.b64 [%0], {%1,%2,%3,%4};"
        :: "l"(p), "l"(v[0]), "l"(v[1]), "l"(v[2]), "l"(v[3]) : "memory");
}

// ---------------------------------------------------------------------------
// MLP kernel — 128 rows/CTA, grid 1024. X register-prefetched; B delivered by
// cp.async.bulk from pre-swizzled weights, issued one round ahead.
// ---------------------------------------------------------------------------
__global__ __launch_bounds__(256, 2)
void mlp_kernel(const float* __restrict__ X,
                const float* __restrict__ W1,
                const float* __restrict__ b1,
                const float* __restrict__ W2,
                const float* __restrict__ b2)
{
    extern __shared__ char smem[];
#if HAS_TCGEN05
#define SM_AHI 1024
#define SM_ALO 17408
#define SM_BHI 33792
#define SM_BLO 50176
#define SM_B1  66560
#define SM_B2  67072
    const uint32_t sb  = smem_u32(smem);
    const int tid = threadIdx.x, wid = tid >> 5, lid = tid & 31;
    const long rowBase = (long)blockIdx.x * 128;

    float* b1s = (float*)(smem + SM_B1);
    float* b2s = (float*)(smem + SM_B2);

    if (wid == 0) { TCG_ALLOC(sb + 0, 256); TCG_RELINQ(); }
    if (tid == 0) { MBAR_INIT(sb + 8, 1); MBAR_INIT(sb + 16, 1); }
    if (tid < 128) { b1s[tid] = b1[tid]; b2s[tid] = b2[tid]; }
    __syncthreads();

    uint32_t tmem;
    asm volatile("ld.shared.b32 %0, [%1];" : "=r"(tmem) : "r"(sb + 0));

    const uint32_t idesc = (1u << 4) | (1u << 7) | (1u << 10) |
                           ((DOUT / 8) << 17) | ((128 / 16) << 24);
    const uint64_t adhi = mk_desc(sb + SM_AHI);
    const uint64_t adlo = mk_desc(sb + SM_ALO);
    const uint64_t bdhi = mk_desc(sb + SM_BHI);
    const uint64_t bdlo = mk_desc(sb + SM_BLO);

    uint32_t parM = 0, parB = 0;

    // chunk source table for rounds 0..5 (W1 c0..c3, W2 c0..c1)
    const char* hi_src[6] = {
        (const char*)g_w1s_hi,         (const char*)g_w1s_hi + 16384,
        (const char*)g_w1s_hi + 32768, (const char*)g_w1s_hi + 49152,
        (const char*)g_w2s_hi,         (const char*)g_w2s_hi + 16384 };
    const char* lo_src[6] = {
        (const char*)g_w1s_lo,         (const char*)g_w1s_lo + 16384,
        (const char*)g_w1s_lo + 32768, (const char*)g_w1s_lo + 49152,
        (const char*)g_w2s_lo,         (const char*)g_w2s_lo + 16384 };

    // issue B for round 0
    if (tid == 0) {
        MBAR_EXPECT_TX(sb + 16, 32768);
        bulk_cp(sb + SM_BHI, hi_src[0], 16384, sb + 16);
        bulk_cp(sb + SM_BLO, lo_src[0], 16384, sb + 16);
    }

    // per-thread X tile coords
    const int xr = tid >> 3;
    const int c8 = tid & 7;
    const float* Xrow = X + rowBase * DIN;

    // prefetch round-0 X into registers
    float4 pa[4], pb[4];
#pragma unroll
    for (int it = 0; it < 4; it++) {
        int r = it * 32 + xr;
        const float4* src = (const float4*)(Xrow + (size_t)r * DIN + c8 * 8);
        pa[it] = src[0];
        pb[it] = src[1];
    }

    // ================= GEMM1: 4 K-chunks of 64 =================
    for (int kb = 0; kb < 4; kb++) {
        // 1. convert prefetched regs -> A smem
#pragma unroll
        for (int it = 0; it < 4; it++) {
            int r = it * 32 + xr;
            uint32_t h0, l0, h1, l1, h2, l2, h3, l3;
            split2(pa[it].x, pa[it].y, h0, l0);
            split2(pa[it].z, pa[it].w, h1, l1);
            split2(pb[it].x, pb[it].y, h2, l2);
            split2(pb[it].z, pb[it].w, h3, l3);
            uint32_t off = SWZ((uint32_t)(r * 128 + c8 * 16));
            *(uint4*)(smem + SM_AHI + off) = make_uint4(h0, h1, h2, h3);
            *(uint4*)(smem + SM_ALO + off) = make_uint4(l0, l1, l2, l3);
        }
        // 2. prefetch X for round kb+1
        if (kb < 3) {
#pragma unroll
            for (int it = 0; it < 4; it++) {
                int r = it * 32 + xr;
                const float4* src = (const float4*)(Xrow + (size_t)r * DIN + (kb + 1) * 64 + c8 * 8);
                pa[it] = src[0];
                pb[it] = src[1];
            }
        }
        // 3. wait B chunk kb, then MMA
        mbar_wait(sb + 16, parB); parB ^= 1;
        __syncthreads();

        if (wid == 0) {
            FENCE_ASYNC_SHARED();
            if (elect_one()) {
#pragma unroll
                for (int ks = 0; ks < 4; ks++)
                    mma_ss(tmem, adhi + ks * 2, bdhi + ks * 2, idesc, (kb > 0) || (ks > 0));
#pragma unroll
                for (int ks = 0; ks < 4; ks++)
                    mma_ss(tmem, adhi + ks * 2, bdlo + ks * 2, idesc, 1);
#pragma unroll
                for (int ks = 0; ks < 4; ks++)
                    mma_ss(tmem, adlo + ks * 2, bdhi + ks * 2, idesc, 1);
                TCG_COMMIT(sb + 8);
            }
        }
        mbar_wait(sb + 8, parM); parM ^= 1;
        TCG_FENCE_AFTER();
        // 4. MMA kb done -> safe to refill B buffer for round kb+1
        if (tid == 0 && kb < 5 - 0) {
            int nxt = kb + 1;
            if (nxt < 6) {
                MBAR_EXPECT_TX(sb + 16, 32768);
                bulk_cp(sb + SM_BHI, hi_src[nxt], 16384, sb + 16);
                bulk_cp(sb + SM_BLO, lo_src[nxt], 16384, sb + 16);
            }
        }
    }

    // ================= GEMM2: 2 K-chunks of 64 =================
    for (int c2 = 0; c2 < 2; c2++) {
        if (wid < 4) {
            int row = wid * 32 + lid;
#pragma unroll
            for (int part = 0; part < 4; part++) {
                uint32_t r16[16];
                LDTM_X16(r16, tmem + c2 * 64 + part * 16);
                TCG_WAIT_LD();
#pragma unroll
                for (int grp = 0; grp < 2; grp++) {
                    uint32_t hs[4], ls[4];
#pragma unroll
                    for (int q = 0; q < 4; q++) {
                        int c = grp * 8 + q * 2;
                        float x0 = __uint_as_float(r16[c])     + b1s[c2 * 64 + part * 16 + c];
                        float x1 = __uint_as_float(r16[c + 1]) + b1s[c2 * 64 + part * 16 + c + 1];
                        x0 = fmaxf(x0, 0.f);
                        x1 = fmaxf(x1, 0.f);
                        split2(x0, x1, hs[q], ls[q]);
                    }
                    uint32_t off = SWZ((uint32_t)(row * 128 + (part * 16 + grp * 8) * 2));
                    *(uint4*)(smem + SM_AHI + off) = make_uint4(hs[0], hs[1], hs[2], hs[3]);
                    *(uint4*)(smem + SM_ALO + off) = make_uint4(ls[0], ls[1], ls[2], ls[3]);
                }
            }
        }
        mbar_wait(sb + 16, parB); parB ^= 1;
        __syncthreads();

        if (wid == 0) {
            FENCE_ASYNC_SHARED();
            if (elect_one()) {
#pragma unroll
                for (int ks = 0; ks < 4; ks++)
                    mma_ss(tmem + 128, adhi + ks * 2, bdhi + ks * 2, idesc, (c2 > 0) || (ks > 0));
#pragma unroll
                for (int ks = 0; ks < 4; ks++)
                    mma_ss(tmem + 128, adhi + ks * 2, bdlo + ks * 2, idesc, 1);
#pragma unroll
                for (int ks = 0; ks < 4; ks++)
                    mma_ss(tmem + 128, adlo + ks * 2, bdhi + ks * 2, idesc, 1);
                TCG_COMMIT(sb + 8);
            }
        }
        mbar_wait(sb + 8, parM); parM ^= 1;
        TCG_FENCE_AFTER();
        if (tid == 0 && c2 == 0) {
            MBAR_EXPECT_TX(sb + 16, 32768);
            bulk_cp(sb + SM_BHI, hi_src[5], 16384, sb + 16);
            bulk_cp(sb + SM_BLO, lo_src[5], 16384, sb + 16);
        }
    }

    // ================= Epilogue: bf16(D2 + b2) -> g_h =================
    if (wid < 4) {
        int row = wid * 32 + lid;
        __nv_bfloat16* dst = g_h + (size_t)(rowBase + row) * DOUT;
#pragma unroll
        for (int grp = 0; grp < 4; grp++) {
            uint32_t r32[32];
            LDTM_X32(r32, tmem + 128 + grp * 32);
            TCG_WAIT_LD();
            uint64_t w64[8];
#pragma unroll
            for (int q = 0; q < 8; q++) {
                float x0 = __uint_as_float(r32[q * 4 + 0]) + b2s[grp * 32 + q * 4 + 0];
                float x1 = __uint_as_float(r32[q * 4 + 1]) + b2s[grp * 32 + q * 4 + 1];
                float x2 = __uint_as_float(r32[q * 4 + 2]) + b2s[grp * 32 + q * 4 + 2];
                float x3 = __uint_as_float(r32[q * 4 + 3]) + b2s[grp * 32 + q * 4 + 3];
                uint32_t wlo = pack_bf16x2(x0, x1);
                uint32_t whi = pack_bf16x2(x2, x3);
                w64[q] = (uint64_t)wlo | ((uint64_t)whi << 32);
            }
            stg_evl4x64(dst + grp * 32,      w64);
            stg_evl4x64(dst + grp * 32 + 16, w64 + 4);
        }
        TCG_FENCE_BEFORE();
    }
    __syncthreads();
    if (tid == 0) { MBAR_INVAL(sb + 8); MBAR_INVAL(sb + 16); }
    __syncthreads();
    if (wid == 0) TCG_DEALLOC(tmem, 256);

#else  // ===================== fp32 FFMA fallback =====================
    float (*xs)[68]   = (float (*)[68])(smem);
    float (*ws)[128]  = (float (*)[128])(smem + 32 * 68 * 4);
    float (*h1T)[68]  = (float (*)[68])(smem + 32 * 68 * 4 + 32 * 128 * 4);

    const int tid = threadIdx.x;
    const int tr  = tid >> 5;
    const int tc  = tid & 31;

    for (int half = 0; half < 2; half++) {
        const long rowBase = (long)blockIdx.x * 128 + half * 64;
        float acc[8][4];
#pragma unroll
        for (int r = 0; r < 8; r++)
#pragma unroll
            for (int c = 0; c < 4; c++) acc[r][c] = 0.f;

        for (int kb = 0; kb < DIN; kb += 32) {
#pragma unroll
            for (int it = 0; it < 2; it++) {
                int f = tid + it * 256;
                int r  = f >> 3;
                int k4 = f & 7;
                float4 v = *(const float4*)(X + (rowBase + r) * DIN + kb + k4 * 4);
                xs[k4 * 4 + 0][r] = v.x;
                xs[k4 * 4 + 1][r] = v.y;
                xs[k4 * 4 + 2][r] = v.z;
                xs[k4 * 4 + 3][r] = v.w;
            }
#pragma unroll
            for (int it = 0; it < 4; it++) {
                int f  = tid + it * 256;
                int kr = f >> 5;
                int c4 = f & 31;
                *(float4*)&ws[kr][c4 * 4] =
                    *(const float4*)(W1 + (size_t)(kb + kr) * DOUT + c4 * 4);
            }
            __syncthreads();
#pragma unroll
            for (int kk = 0; kk < 32; kk++) {
                float4 xa = *(float4*)&xs[kk][tr * 8];
                float4 xb = *(float4*)&xs[kk][tr * 8 + 4];
                float4 w  = *(float4*)&ws[kk][tc * 4];
                float xr8[8] = {xa.x, xa.y, xa.z, xa.w, xb.x, xb.y, xb.z, xb.w};
                float wr[4] = {w.x, w.y, w.z, w.w};
#pragma unroll
                for (int r = 0; r < 8; r++)
#pragma unroll
                    for (int c = 0; c < 4; c++)
                        acc[r][c] = fmaf(xr8[r], wr[c], acc[r][c]);
            }
            __syncthreads();
        }
        {
            float bb[4];
#pragma unroll
            for (int c = 0; c < 4; c++) bb[c] = b1[tc * 4 + c];
#pragma unroll
            for (int r = 0; r < 8; r++)
#pragma unroll
                for (int c = 0; c < 4; c++) {
                    float v = acc[r][c] + bb[c];
                    h1T[tc * 4 + c][tr * 8 + r] = fmaxf(v, 0.f);
                    acc[r][c] = 0.f;
                }
        }
        __syncthreads();

        for (int kb = 0; kb < DOUT; kb += 32) {
#pragma unroll
            for (int it = 0; it < 4; it++) {
                int f  = tid + it * 256;
                int kr = f >> 5;
                int c4 = f & 31;
                *(float4*)&ws[kr][c4 * 4] =
                    *(const float4*)(W2 + (size_t)(kb + kr) * DOUT + c4 * 4);
            }
            __syncthreads();
#pragma unroll
            for (int kk = 0; kk < 32; kk++) {
                float4 xa = *(float4*)&h1T[kb + kk][tr * 8];
                float4 xb = *(float4*)&h1T[kb + kk][tr * 8 + 4];
                float4 w  = *(float4*)&ws[kk][tc * 4];
                float xr8[8] = {xa.x, xa.y, xa.z, xa.w, xb.x, xb.y, xb.z, xb.w};
                float wr[4] = {w.x, w.y, w.z, w.w};
#pragma unroll
                for (int r = 0; r < 8; r++)
#pragma unroll
                    for (int c = 0; c < 4; c++)
                        acc[r][c] = fmaf(xr8[r], wr[c], acc[r][c]);
            }
            __syncthreads();
        }
        {
            float bb[4];
#pragma unroll
            for (int c = 0; c < 4; c++) bb[c] = b2[tc * 4 + c];
#pragma unroll
            for (int r = 0; r < 8; r++) {
                float x0 = acc[r][0] + bb[0];
                float x1 = acc[r][1] + bb[1];
                float x2 = acc[r][2] + bb[2];
                float x3 = acc[r][3] + bb[3];
                uint2 o;
                o.x = pack_bf16x2(x0, x1);
                o.y = pack_bf16x2(x2, x3);
                *(uint2*)(g_h + (rowBase + tr * 8 + r) * DOUT + tc * 4) = o;
            }
        }
        __syncthreads();
    }
#endif
}

// ---------------------------------------------------------------------------
// Gather kernel, n-PAIR sliced (R11/R12 version, ~at DRAM limit)
// ---------------------------------------------------------------------------
__global__ __launch_bounds__(256)
void gather_add_kernel(const float* __restrict__ up,
                       const int*   __restrict__ idx,
                       float*       __restrict__ out)
{
    const int n2     = blockIdx.x >> 12;            // 0..3
    const int ublock = blockIdx.x & 4095;           // 0..4095
    const int lane   = threadIdx.x & 7;             // 16-bf16 chunk id
    const int nsub   = (threadIdx.x >> 3) & 1;      // 0/1
    const int n      = n2 * 2 + nsub;
    const long u     = (long)ublock * 16 + (threadIdx.x >> 4);
    const long row   = u * NNm + n;                 // output row (u,n)

    const int* ip = idx + row * 3;
    int i0 = __ldg(ip + 0);
    int i1 = __ldg(ip + 1);
    int i2 = __ldg(ip + 2);

    const __nv_bfloat16* p0 = g_h + (size_t)(i0 * NNm + n) * DOUT + lane * 16;
    const __nv_bfloat16* p1 = g_h + (size_t)(i1 * NNm + n) * DOUT + lane * 16;
    const __nv_bfloat16* p2 = g_h + (size_t)(i2 * NNm + n) * DOUT + lane * 16;

    uint64_t ga[4], gb[4], gc[4];
    ldg_evl4x64(p0, ga);
    ldg_evl4x64(p1, gb);
    ldg_evl4x64(p2, gc);

    const float4* upp = (const float4*)(up + row * DOUT + lane * 16);
    float4 u4[4];
    u4[0] = __ldcs(upp + 0);
    u4[1] = __ldcs(upp + 1);
    u4[2] = __ldcs(upp + 2);
    u4[3] = __ldcs(upp + 3);

    const float inv3 = 1.0f / 3.0f;
    float4 o[4];
    float* uo = (float*)u4;
    float* oo = (float*)o;
#pragma unroll
    for (int q = 0; q < 4; q++) {
#pragma unroll
        for (int hw = 0; hw < 2; hw++) {
            uint32_t wa = (uint32_t)(ga[q] >> (hw * 32));
            uint32_t wb = (uint32_t)(gb[q] >> (hw * 32));
            uint32_t wc = (uint32_t)(gc[q] >> (hw * 32));
            float a0 = __uint_as_float(wa << 16), a1 = __uint_as_float(wa & 0xFFFF0000u);
            float b0 = __uint_as_float(wb << 16), b1 = __uint_as_float(wb & 0xFFFF0000u);
            float c0 = __uint_as_float(wc << 16), c1 = __uint_as_float(wc & 0xFFFF0000u);
            int e = q * 4 + hw * 2;
            oo[e + 0] = fmaf(a0 + b0 + c0, inv3, uo[e + 0]);
            oo[e + 1] = fmaf(a1 + b1 + c1, inv3, uo[e + 1]);
        }
    }

    float4* op = (float4*)(out + row * DOUT + lane * 16);
    __stcs(op + 0, o[0]);
    __stcs(op + 1, o[1]);
    __stcs(op + 2, o[2]);
    __stcs(op + 3, o[3]);
}

// ---------------------------------------------------------------------------
// Launch: inputs = down_features, up_features, idx, W1, b1, W2, b2
// ---------------------------------------------------------------------------
extern "C" void kernel_launch(void* const* d_in, const int* in_sizes, int n_in,
                              void* d_out, int out_size)
{
    const float* down = (const float*)d_in[0];
    const float* up   = (const float*)d_in[1];
    const int*   idx  = (const int*)  d_in[2];
    const float* W1   = (const float*)d_in[3];
    const float* b1   = (const float*)d_in[4];
    const float* W2   = (const float*)d_in[5];
    const float* b2   = (const float*)d_in[6];
    float* out = (float*)d_out;

    static int smem_set = 0;
    if (!smem_set) {
        cudaFuncSetAttribute(mlp_kernel,
                             cudaFuncAttributeMaxDynamicSharedMemorySize, SMEM_TOTAL);
        smem_set = 1;
    }

    // 1. Split weights into bf16 hi/lo, pre-swizzled chunk images
    wsplit_kernel<<<192, 256>>>(W1, W2);

    // 2. MLP -> g_h bf16 (bulk-copy B, prefetched X)
    mlp_kernel<<<M_ROWS / 128, 256, SMEM_TOTAL>>>(down, W1, b1, W2, b2);

    // 3. Gather + mean + add, n-pair sliced (4 passes x 4096 blocks)
    gather_add_kernel<<<4 * 4096, 256>>>(up, idx, out);
}